// round 14
// baseline (speedup 1.0000x reference)
#include <cuda_runtime.h>
#include <cuda_bf16.h>
#include <math.h>
#include <stdint.h>

// ---------------------------------------------------------------------------
// EncoderLayer R14: mma.sync m16n8k16 bf16 (fp32 acc, bf16x3 split).
// vs R12: 512-thread mma CTAs with 4x4 warp grid, 32x32 per-warp tiles
// (acc=32 regs -> no spills at the 128-reg/512-thread cap), double-buffered
// B so weight copies overlap the epilogue. One 128-row tile per CTA iter.
// ---------------------------------------------------------------------------

#define RES   12000
#define KN    48
#define H     128
#define HH    (H*H)
#define TILE_FLOATS (KN*H)
#define NEDGE (RES*KN)
#define NTILES (NEDGE/128)        // 4500

typedef unsigned long long u64;
typedef unsigned int u32;

// Scratch globals (sanctioned no-alloc path)
__device__ float g_PA1[RES*H];
__device__ float g_PB1[RES*H];
__device__ float g_PA2[RES*H];
__device__ float g_PB2[RES*H];
__device__ float g_NODE1[RES*H];
__device__ float g_FFH[(size_t)RES*4*H];
__device__ float g_Y2[(size_t)NEDGE*H];                  // msg y2 scratch
#define ASZ 34816                                        // 128 rows * 272B
__device__ __align__(16) unsigned char g_WT[2][3][2*ASZ];

__device__ __forceinline__ float gelu(float x){
    return 0.5f * x * (1.0f + erff(x * 0.7071067811865475f));
}

// ---------------- packed f32x2 helpers (FFMA2 small kernels) ---------------
__device__ __forceinline__ u64 pk2(float x){
    u64 r; asm("mov.b64 %0, {%1, %1};" : "=l"(r) : "f"(x)); return r;
}
__device__ __forceinline__ u64 pk(float lo, float hi){
    u64 r; asm("mov.b64 %0, {%1, %2};" : "=l"(r) : "f"(lo), "f"(hi)); return r;
}
__device__ __forceinline__ u64 fma2(u64 a, u64 b, u64 c){
    u64 d; asm("fma.rn.f32x2 %0, %1, %2, %3;" : "=l"(d) : "l"(a), "l"(b), "l"(c)); return d;
}
__device__ __forceinline__ float2 up2(u64 v){
    float lo, hi; asm("mov.b64 {%0, %1}, %2;" : "=f"(lo), "=f"(hi) : "l"(v));
    return make_float2(lo, hi);
}

__device__ __forceinline__ void mm12(const float* __restrict__ xr,
                                     const float* __restrict__ ws,
                                     int tx, u64* __restrict__ acc){
    const float4* wp = (const float4*)ws + tx;
    #pragma unroll 1
    for (int k = 0; k < H; k += 4){
        float4 wk0 = wp[(k+0)*(H/4)];
        float4 wk1 = wp[(k+1)*(H/4)];
        float4 wk2 = wp[(k+2)*(H/4)];
        float4 wk3 = wp[(k+3)*(H/4)];
        u64 wl0 = pk(wk0.x, wk0.y), wh0 = pk(wk0.z, wk0.w);
        u64 wl1 = pk(wk1.x, wk1.y), wh1 = pk(wk1.z, wk1.w);
        u64 wl2 = pk(wk2.x, wk2.y), wh2 = pk(wk2.z, wk2.w);
        u64 wl3 = pk(wk3.x, wk3.y), wh3 = pk(wk3.z, wk3.w);
        #pragma unroll
        for (int r = 0; r < 12; r++){
            float4 xv = *(const float4*)(xr + r*H + k);
            u64* a = acc + r*2;
            u64 s;
            s = pk2(xv.x); a[0] = fma2(s, wl0, a[0]); a[1] = fma2(s, wh0, a[1]);
            s = pk2(xv.y); a[0] = fma2(s, wl1, a[0]); a[1] = fma2(s, wh1, a[1]);
            s = pk2(xv.z); a[0] = fma2(s, wl2, a[0]); a[1] = fma2(s, wh2, a[1]);
            s = pk2(xv.w); a[0] = fma2(s, wl3, a[0]); a[1] = fma2(s, wh3, a[1]);
        }
    }
}

template<int NT>
__device__ __forceinline__ void copyN(float* dst, const float* src, int tid, int nfloats){
    const float4* s = (const float4*)src; float4* d = (float4*)dst;
    #pragma unroll 4
    for (int i = tid; i < nfloats/4; i += NT) d[i] = s[i];
}

// ==================== FFMA2 kernels (proj / ff1 / ff2) =====================
__global__ void __launch_bounds__(256, 2)
proj_kernel(const float* __restrict__ src, const float* __restrict__ w,
            const float* __restrict__ bias, int sel){
    extern __shared__ float sm[];
    float* ws = sm; float* xs = sm + HH;
    int tid = threadIdx.x, tx = tid & 31, ty = tid >> 5;
    copyN<256>(ws, w, tid, HH);
    copyN<256>(xs, src + (size_t)blockIdx.x*2*TILE_FLOATS, tid, 2*TILE_FLOATS);
    __syncthreads();
    u64 acc[24];
    #pragma unroll
    for (int q = 0; q < 24; q++) acc[q] = 0ull;
    mm12(xs + ty*12*H, ws, tx, acc);
    float4 bv = make_float4(0.f,0.f,0.f,0.f);
    if (bias) bv = *(const float4*)(bias + 4*tx);
    float* outp = (sel==0) ? g_PA1 : (sel==1) ? g_PB1 : (sel==2) ? g_PA2 : g_PB2;
    int base = blockIdx.x * 96 + ty*12;
    #pragma unroll
    for (int r = 0; r < 12; r++){
        float2 v0 = up2(acc[r*2]), v1 = up2(acc[r*2+1]);
        *(float4*)(outp + (size_t)(base+r)*H + 4*tx) =
            make_float4(v0.x+bv.x, v0.y+bv.y, v1.x+bv.z, v1.y+bv.w);
    }
}

__global__ void __launch_bounds__(256, 2)
ff1_kernel(const float* __restrict__ w, const float* __restrict__ bias){
    extern __shared__ float sm[];
    float* ws = sm; float* xs = sm + HH;
    int tid = threadIdx.x, tx = tid & 31, ty = tid >> 5;
    int n0 = blockIdx.y * H;
    {
        float4* d = (float4*)ws;
        #pragma unroll 4
        for (int i = tid; i < HH/4; i += 256){
            int k = i >> 5, c = i & 31;
            d[i] = *(const float4*)(w + (size_t)k*(4*H) + n0 + 4*c);
        }
    }
    copyN<256>(xs, g_NODE1 + (size_t)blockIdx.x*2*TILE_FLOATS, tid, 2*TILE_FLOATS);
    __syncthreads();
    u64 acc[24];
    #pragma unroll
    for (int q = 0; q < 24; q++) acc[q] = 0ull;
    mm12(xs + ty*12*H, ws, tx, acc);
    float4 bv = *(const float4*)(bias + n0 + 4*tx);
    int base = blockIdx.x * 96 + ty*12;
    #pragma unroll
    for (int r = 0; r < 12; r++){
        float2 v0 = up2(acc[r*2]), v1 = up2(acc[r*2+1]);
        *(float4*)(g_FFH + (size_t)(base+r)*(4*H) + n0 + 4*tx) =
            make_float4(gelu(v0.x+bv.x), gelu(v0.y+bv.y),
                        gelu(v1.x+bv.z), gelu(v1.y+bv.w));
    }
}

__global__ void __launch_bounds__(256, 2)
ff2_kernel(const float* __restrict__ w, const float* __restrict__ bias,
           const float* __restrict__ ln2_g, const float* __restrict__ ln2_b,
           float* __restrict__ out_node){
    extern __shared__ float sm[];
    float* ws = sm; float* xs = sm + HH;
    int tid = threadIdx.x, tx = tid & 31, ty = tid >> 5;
    int base = blockIdx.x * 96;
    u64 acc[24];
    #pragma unroll
    for (int q = 0; q < 24; q++) acc[q] = 0ull;
    for (int c = 0; c < 4; c++){
        copyN<256>(ws, w + (size_t)c*H*H, tid, HH);
        {
            float4* d = (float4*)xs;
            #pragma unroll
            for (int i = tid; i < 2*TILE_FLOATS/4; i += 256){
                int m = i >> 5, cc = i & 31;
                d[i] = *(const float4*)(g_FFH + (size_t)(base+m)*(4*H) + c*H + 4*cc);
            }
        }
        __syncthreads();
        mm12(xs + ty*12*H, ws, tx, acc);
        __syncthreads();
    }
    float4 bv = *(const float4*)(bias + 4*tx);
    float4 lg = *(const float4*)(ln2_g + 4*tx);
    float4 lb = *(const float4*)(ln2_b + 4*tx);
    #pragma unroll
    for (int r = 0; r < 12; r++){
        int row = base + ty*12 + r;
        float4 a = *(const float4*)(g_NODE1 + (size_t)row*H + 4*tx);
        float2 v0 = up2(acc[r*2]), v1 = up2(acc[r*2+1]);
        float x0 = v0.x+bv.x+a.x, x1 = v0.y+bv.y+a.y;
        float x2 = v1.x+bv.z+a.z, x3 = v1.y+bv.w+a.w;
        float s = x0+x1+x2+x3, q = x0*x0+x1*x1+x2*x2+x3*x3;
        #pragma unroll
        for (int off = 16; off; off >>= 1){
            s += __shfl_xor_sync(0xffffffffu, s, off);
            q += __shfl_xor_sync(0xffffffffu, q, off);
        }
        float mean = s * (1.0f/H);
        float rstd = rsqrtf(q*(1.0f/H) - mean*mean + 1e-5f);
        *(float4*)(out_node + (size_t)row*H + 4*tx) =
            make_float4((x0-mean)*rstd*lg.x+lb.x, (x1-mean)*rstd*lg.y+lb.y,
                        (x2-mean)*rstd*lg.z+lb.z, (x3-mean)*rstd*lg.w+lb.w);
    }
}

// ===================== mma.sync machinery (base target) ====================
#define PKB 272
#define OFF_A    1024
#define OFF_B0   (OFF_A + 2*ASZ)              // 70656
#define OFF_B1   (OFF_B0 + 2*ASZ)             // 140288
#define OFF_RED  (OFF_B1 + 2*ASZ)             // 209920 (4KB)
#define OFF_BIAS (OFF_RED + 4096)             // 214016 (2KB)
#define SMEM_MMA (OFF_BIAS + 2048)            // 216064

__device__ __forceinline__ u32 smem_u32(const void* p){
    u32 a;
    asm("{ .reg .u64 t; cvta.to.shared.u64 t, %1; cvt.u32.u64 %0, t; }"
        : "=r"(a) : "l"(p));
    return a;
}
__device__ __forceinline__ void ldsm4(u32 r[4], u32 addr){
    asm volatile("ldmatrix.sync.aligned.m8n8.x4.shared.b16 {%0,%1,%2,%3}, [%4];"
        : "=r"(r[0]), "=r"(r[1]), "=r"(r[2]), "=r"(r[3]) : "r"(addr));
}
__device__ __forceinline__ void mma_bf16(float* d, const u32* a, const u32* b){
    asm volatile("mma.sync.aligned.m16n8k16.row.col.f32.bf16.bf16.f32 "
        "{%0,%1,%2,%3}, {%4,%5,%6,%7}, {%8,%9}, {%0,%1,%2,%3};"
        : "+f"(d[0]), "+f"(d[1]), "+f"(d[2]), "+f"(d[3])
        : "r"(a[0]), "r"(a[1]), "r"(a[2]), "r"(a[3]), "r"(b[0]), "r"(b[1]));
}
__device__ __forceinline__ void split2(float x, float y, u32& hi, u32& lo){
    __nv_bfloat16 hx = __float2bfloat16_rn(x), hy = __float2bfloat16_rn(y);
    float rx = x - __bfloat162float(hx), ry = y - __bfloat162float(hy);
    __nv_bfloat16 lx = __float2bfloat16_rn(rx), ly = __float2bfloat16_rn(ry);
    hi = (u32)__bfloat16_as_ushort(hx) | ((u32)__bfloat16_as_ushort(hy) << 16);
    lo = (u32)__bfloat16_as_ushort(lx) | ((u32)__bfloat16_as_ushort(ly) << 16);
}

// 3-pass split GEMM, warp tile 32x32: rows mw*32..+31, cols nw*32..+31.
// acc[2][4][4]: mt = 16-row half, nt = 8-col group.
__device__ __forceinline__ void gemm3(u32 abase0, u32 bbase0, int lane, int mw, int nw,
                                      float acc[2][4][4]){
    #pragma unroll
    for (int mt = 0; mt < 2; mt++)
        #pragma unroll
        for (int nt = 0; nt < 4; nt++)
            #pragma unroll
            for (int c = 0; c < 4; c++) acc[mt][nt][c] = 0.f;
    u32 aoff = (u32)(mw*32 + (lane & 15))*PKB + (u32)((lane >> 4) * 16);
    u32 boff = (u32)(nw*32 + ((lane >> 4) << 3) + (lane & 7))*PKB
             + (u32)(((lane >> 3) & 1) * 16);
    #pragma unroll 1
    for (int pass = 0; pass < 3; pass++){
        u32 abase = abase0 + (pass==2 ? ASZ : 0) + aoff;
        u32 bbase = bbase0 + (pass==1 ? ASZ : 0) + boff;
        #pragma unroll
        for (int ks = 0; ks < 8; ks++){
            u32 kb = (u32)(ks*32);
            u32 a0[4], a1[4], b[2][4];
            ldsm4(a0, abase + kb);
            ldsm4(a1, abase + 16*PKB + kb);
            ldsm4(b[0], bbase + kb);
            ldsm4(b[1], bbase + 16*PKB + kb);
            #pragma unroll
            for (int mt = 0; mt < 2; mt++)
                #pragma unroll
                for (int nt = 0; nt < 4; nt++)
                    mma_bf16(acc[mt][nt], mt ? a1 : a0, &b[nt>>1][(nt&1)*2]);
        }
    }
}

__device__ __forceinline__ void copyB(char* dst, const unsigned char* src, int tid){
    uint4* d = (uint4*)dst; const uint4* s = (const uint4*)src;
    #pragma unroll
    for (int i = tid; i < (2*ASZ)/16; i += 512) d[i] = s[i];
}

// build A hi/lo from a 128x128 fp32 tile, 512 threads: (row, quarter)
__device__ __forceinline__ void buildA(char* Ahi, char* Alo,
                                       const float* __restrict__ src128, int tid){
    int row = tid & 127, qt = tid >> 7;
    const float2* src = (const float2*)(src128 + (size_t)row*H + qt*32);
    u32 base = (u32)row*PKB + (u32)qt*64;
    #pragma unroll
    for (int j = 0; j < 16; j++){
        float2 v = src[j];
        u32 hi, lo; split2(v.x, v.y, hi, lo);
        *(u32*)(Ahi + base + 4*j) = hi;
        *(u32*)(Alo + base + 4*j) = lo;
    }
}

// prebuild W^T hi/lo images, padded
__global__ void prep_wt_kernel(const float* __restrict__ w0,
                               const float* __restrict__ w1,
                               const float* __restrict__ w2, int stage){
    int bx = blockIdx.x;              // 384 = 3 mats * 128 n-rows
    int mat = bx >> 7, n = bx & 127, k = threadIdx.x;
    const float* w = (mat==0) ? w0 : (mat==1) ? w1 : w2;
    float x = w[k*H + n];             // B^T[n][k] = W[k][n]
    __nv_bfloat16 h = __float2bfloat16_rn(x);
    float l = x - __bfloat162float(h);
    __nv_bfloat16 hl = __float2bfloat16_rn(l);
    u32 off = (u32)n*PKB + (u32)k*2;
    *(__nv_bfloat16*)(&g_WT[stage][mat][0]   + off) = h;
    *(__nv_bfloat16*)(&g_WT[stage][mat][ASZ] + off) = hl;
}

// ---------------------- msg stage mma kernel -------------------------------
__global__ void __launch_bounds__(512, 1)
msg_mma_kernel(const float* __restrict__ edge_h, const int* __restrict__ edge_idx,
               const float* __restrict__ b1, const float* __restrict__ b2){
    extern __shared__ char smc[];
    u32 sb = smem_u32(smc);
    char* Ahi = smc + OFF_A; char* Alo = Ahi + ASZ;
    float* sb1 = (float*)(smc + OFF_BIAS);
    float* sb2 = sb1 + 128;
    int tid = threadIdx.x, lane = tid & 31, w = tid >> 5;
    int mw = w & 3, nw = w >> 2;                // 4x4 warp grid
    int g = lane >> 2, t2 = (lane & 3)*2;
    u32 abase0 = sb + OFF_A;
    if (tid < 128){ sb1[tid] = b1[tid]; sb2[tid] = b2[tid]; }

    for (int tile = blockIdx.x; tile < NTILES; tile += gridDim.x){
        buildA(Ahi, Alo, edge_h + (size_t)tile*128*H, tid);
        copyB(smc + OFF_B0, g_WT[0][0], tid);
        int rows[4], jr4[4], ir4[4];
        #pragma unroll
        for (int idx = 0; idx < 4; idx++){
            rows[idx] = mw*32 + (idx>>1)*16 + (idx&1)*8 + g;
            int gr = tile*128 + rows[idx];
            ir4[idx] = gr/48; jr4[idx] = edge_idx[gr];
        }
        __syncthreads();
        #pragma unroll 1
        for (int layer = 0; layer < 3; layer++){
            u32 bbase0 = sb + ((layer & 1) ? OFF_B1 : OFF_B0);
            float acc[2][4][4];
            gemm3(abase0, bbase0, lane, mw, nw, acc);
            __syncthreads();                      // A/B reads complete
            if (layer < 2)
                copyB(smc + ((layer & 1) ? OFF_B0 : OFF_B1), g_WT[0][layer+1], tid);
            if (layer < 2){
                #pragma unroll
                for (int mt = 0; mt < 2; mt++)
                #pragma unroll
                for (int rr = 0; rr < 2; rr++){
                    int idx = mt*2 + rr, row = rows[idx];
                    const float* pa = g_PA1 + (size_t)ir4[idx]*H;
                    const float* pb = g_PB1 + (size_t)jr4[idx]*H;
                    #pragma unroll
                    for (int nt = 0; nt < 4; nt++){
                        int col = nw*32 + nt*8 + t2;
                        float v0 = acc[mt][nt][rr*2], v1 = acc[mt][nt][rr*2+1];
                        if (layer == 0){
                            float2 a = *(const float2*)(pa + col);
                            float2 b = *(const float2*)(pb + col);
                            v0 = gelu(v0 + a.x + b.x); v1 = gelu(v1 + a.y + b.y);
                        } else {
                            v0 = gelu(v0 + sb1[col]); v1 = gelu(v1 + sb1[col+1]);
                        }
                        u32 hi, lo; split2(v0, v1, hi, lo);
                        u32 off = (u32)row*PKB + (u32)col*2;
                        *(u32*)(Ahi + off) = hi; *(u32*)(Alo + off) = lo;
                    }
                }
            } else {
                #pragma unroll
                for (int mt = 0; mt < 2; mt++)
                #pragma unroll
                for (int rr = 0; rr < 2; rr++){
                    int idx = mt*2 + rr;
                    size_t gr = (size_t)tile*128 + rows[idx];
                    #pragma unroll
                    for (int nt = 0; nt < 4; nt++){
                        int col = nw*32 + nt*8 + t2;
                        *(float2*)(g_Y2 + gr*H + col) = make_float2(
                            acc[mt][nt][rr*2]   + sb2[col],
                            acc[mt][nt][rr*2+1] + sb2[col+1]);
                    }
                }
            }
            __syncthreads();                      // A/B writes visible
        }
    }
}

// ---------------------- edge stage mma kernel ------------------------------
__global__ void __launch_bounds__(512, 1)
edge_mma_kernel(const float* __restrict__ edge_h, const int* __restrict__ edge_idx,
                const float* __restrict__ b1, const float* __restrict__ b2,
                const float* __restrict__ lne_g, const float* __restrict__ lne_b,
                float* __restrict__ out_edge){
    extern __shared__ char smc[];
    u32 sb = smem_u32(smc);
    char* Ahi = smc + OFF_A; char* Alo = Ahi + ASZ;
    float2* red = (float2*)(smc + OFF_RED);       // [row*4 + nw]
    float* sb1 = (float*)(smc + OFF_BIAS);
    float* sb2 = sb1 + 128;
    float* slg = sb2 + 128;
    float* slb = slg + 128;
    int tid = threadIdx.x, lane = tid & 31, w = tid >> 5;
    int mw = w & 3, nw = w >> 2;
    int g = lane >> 2, t2 = (lane & 3)*2;
    u32 abase0 = sb + OFF_A;
    if (tid < 128){ sb1[tid]=b1[tid]; sb2[tid]=b2[tid]; slg[tid]=lne_g[tid]; slb[tid]=lne_b[tid]; }

    for (int tile = blockIdx.x; tile < NTILES; tile += gridDim.x){
        buildA(Ahi, Alo, edge_h + (size_t)tile*128*H, tid);
        copyB(smc + OFF_B0, g_WT[1][0], tid);
        int rows[4], jr4[4], ir4[4];
        #pragma unroll
        for (int idx = 0; idx < 4; idx++){
            rows[idx] = mw*32 + (idx>>1)*16 + (idx&1)*8 + g;
            int gr = tile*128 + rows[idx];
            ir4[idx] = gr/48; jr4[idx] = edge_idx[gr];
        }
        __syncthreads();
        #pragma unroll 1
        for (int layer = 0; layer < 3; layer++){
            u32 bbase0 = sb + ((layer & 1) ? OFF_B1 : OFF_B0);
            float acc[2][4][4];
            gemm3(abase0, bbase0, lane, mw, nw, acc);
            __syncthreads();
            if (layer < 2)
                copyB(smc + ((layer & 1) ? OFF_B0 : OFF_B1), g_WT[1][layer+1], tid);
            if (layer < 2){
                #pragma unroll
                for (int mt = 0; mt < 2; mt++)
                #pragma unroll
                for (int rr = 0; rr < 2; rr++){
                    int idx = mt*2 + rr, row = rows[idx];
                    const float* pa = g_PA2 + (size_t)ir4[idx]*H;
                    const float* pb = g_PB2 + (size_t)jr4[idx]*H;
                    #pragma unroll
                    for (int nt = 0; nt < 4; nt++){
                        int col = nw*32 + nt*8 + t2;
                        float v0 = acc[mt][nt][rr*2], v1 = acc[mt][nt][rr*2+1];
                        if (layer == 0){
                            float2 a = *(const float2*)(pa + col);
                            float2 b = *(const float2*)(pb + col);
                            v0 = gelu(v0 + a.x + b.x); v1 = gelu(v1 + a.y + b.y);
                        } else {
                            v0 = gelu(v0 + sb1[col]); v1 = gelu(v1 + sb1[col+1]);
                        }
                        u32 hi, lo; split2(v0, v1, hi, lo);
                        u32 off = (u32)row*PKB + (u32)col*2;
                        *(u32*)(Ahi + off) = hi; *(u32*)(Alo + off) = lo;
                    }
                }
                __syncthreads();
            } else {
                // x = D + b2 + edge_h ; per-row LN across 4 nw quarters
                #pragma unroll
                for (int mt = 0; mt < 2; mt++)
                #pragma unroll
                for (int rr = 0; rr < 2; rr++){
                    int idx = mt*2 + rr;
                    size_t gr = (size_t)tile*128 + rows[idx];
                    const float* eh = edge_h + gr*H;
                    float s = 0.f, q = 0.f;
                    #pragma unroll
                    for (int nt = 0; nt < 4; nt++){
                        int col = nw*32 + nt*8 + t2;
                        float2 e = *(const float2*)(eh + col);
                        float v0 = acc[mt][nt][rr*2]   + sb2[col]   + e.x;
                        float v1 = acc[mt][nt][rr*2+1] + sb2[col+1] + e.y;
                        acc[mt][nt][rr*2] = v0; acc[mt][nt][rr*2+1] = v1;
                        s += v0 + v1; q += v0*v0 + v1*v1;
                    }
                    s += __shfl_xor_sync(0xffffffffu, s, 1);
                    q += __shfl_xor_sync(0xffffffffu, q, 1);
                    s += __shfl_xor_sync(0xffffffffu, s, 2);
                    q += __shfl_xor_sync(0xffffffffu, q, 2);
                    if ((lane & 3) == 0) red[rows[idx]*4 + nw] = make_float2(s, q);
                }
                __syncthreads();
                #pragma unroll
                for (int mt = 0; mt < 2; mt++)
                #pragma unroll
                for (int rr = 0; rr < 2; rr++){
                    int idx = mt*2 + rr;
                    size_t gr = (size_t)tile*128 + rows[idx];
                    float2 r0 = red[rows[idx]*4+0], r1 = red[rows[idx]*4+1];
                    float2 r2 = red[rows[idx]*4+2], r3 = red[rows[idx]*4+3];
                    float mean = (r0.x+r1.x+r2.x+r3.x) * (1.0f/H);
                    float var  = (r0.y+r1.y+r2.y+r3.y) * (1.0f/H) - mean*mean;
                    float rstd = rsqrtf(var + 1e-5f);
                    #pragma unroll
                    for (int nt = 0; nt < 4; nt++){
                        int col = nw*32 + nt*8 + t2;
                        float v0 = acc[mt][nt][rr*2], v1 = acc[mt][nt][rr*2+1];
                        *(float2*)(out_edge + gr*H + col) = make_float2(
                            (v0-mean)*rstd*slg[col]   + slb[col],
                            (v1-mean)*rstd*slg[col+1] + slb[col+1]);
                    }
                }
                __syncthreads();
            }
        }
    }
}

// ---------------- k-sum + LN1 over g_Y2 -> NODE1 ---------------------------
__global__ void __launch_bounds__(128)
ksum_kernel(const float* __restrict__ node_h, const float* __restrict__ ln1_g,
            const float* __restrict__ ln1_b){
    __shared__ float sv[130];
    int i = blockIdx.x, c = threadIdx.x;
    const float* y = g_Y2 + (size_t)i*KN*H + c;
    float s = 0.f;
    #pragma unroll 8
    for (int k = 0; k < KN; k++) s += y[(size_t)k*H];
    float v = node_h[(size_t)i*H + c] + s;
    sv[c] = v;
    __syncthreads();
    if (c < 32){
        float a = 0.f, q = 0.f;
        #pragma unroll
        for (int g2 = 0; g2 < 4; g2++){ float x = sv[c + 32*g2]; a += x; q += x*x; }
        #pragma unroll
        for (int off = 16; off; off >>= 1){
            a += __shfl_xor_sync(0xffffffffu, a, off);
            q += __shfl_xor_sync(0xffffffffu, q, off);
        }
        if (c == 0){
            float mean = a * (1.0f/H);
            sv[128] = mean;
            sv[129] = rsqrtf(q*(1.0f/H) - mean*mean + 1e-5f);
        }
    }
    __syncthreads();
    g_NODE1[(size_t)i*H + c] = (v - sv[128]) * sv[129] * ln1_g[c] + ln1_b[c];
}

// ---------------------------------------------------------------------------
extern "C" void kernel_launch(void* const* d_in, const int* in_sizes, int n_in,
                              void* d_out, int out_size){
    const float* node_h  = (const float*)d_in[0];
    const float* edge_h  = (const float*)d_in[1];
    const float* msg_w0  = (const float*)d_in[2];
    const float* msg_b0  = (const float*)d_in[3];
    const float* msg_w1  = (const float*)d_in[4];
    const float* msg_b1  = (const float*)d_in[5];
    const float* msg_w2  = (const float*)d_in[6];
    const float* msg_b2  = (const float*)d_in[7];
    const float* ff_w0   = (const float*)d_in[8];
    const float* ff_b0   = (const float*)d_in[9];
    const float* ff_w1   = (const float*)d_in[10];
    const float* ff_b1   = (const float*)d_in[11];
    const float* edge_w0 = (const float*)d_in[12];
    const float* edge_b0 = (const float*)d_in[13];
    const float* edge_w1 = (const float*)d_in[14];
    const float* edge_b1 = (const float*)d_in[15];
    const float* edge_w2 = (const float*)d_in[16];
    const float* edge_b2 = (const float*)d_in[17];
    const float* ln1_g   = (const float*)d_in[18];
    const float* ln1_b   = (const float*)d_in[19];
    const float* ln2_g   = (const float*)d_in[20];
    const float* ln2_b   = (const float*)d_in[21];
    const float* lne_g   = (const float*)d_in[22];
    const float* lne_b   = (const float*)d_in[23];
    const int*   edge_idx= (const int*)  d_in[24];

    float* out_node = (float*)d_out;
    float* out_edge = out_node + (size_t)RES*H;

    const int SMEM_SMALL = (HH + 2*TILE_FLOATS) * 4;   // 114688
    cudaFuncSetAttribute(proj_kernel, cudaFuncAttributeMaxDynamicSharedMemorySize, SMEM_SMALL);
    cudaFuncSetAttribute(ff1_kernel,  cudaFuncAttributeMaxDynamicSharedMemorySize, SMEM_SMALL);
    cudaFuncSetAttribute(ff2_kernel,  cudaFuncAttributeMaxDynamicSharedMemorySize, SMEM_SMALL);
    cudaFuncSetAttribute(msg_mma_kernel,  cudaFuncAttributeMaxDynamicSharedMemorySize, SMEM_MMA);
    cudaFuncSetAttribute(edge_mma_kernel, cudaFuncAttributeMaxDynamicSharedMemorySize, SMEM_MMA);

    int dev = 0, nsm = 148;
    if (cudaGetDevice(&dev) == cudaSuccess){
        int v = 0;
        if (cudaDeviceGetAttribute(&v, cudaDevAttrMultiProcessorCount, dev) == cudaSuccess && v > 0)
            nsm = v;
    }

    const int NBLK = RES / 96;   // 125

    // W^T image prep (both stages)
    prep_wt_kernel<<<384, 128>>>(msg_w0 + 256*H,  msg_w1,  msg_w2,  0);
    prep_wt_kernel<<<384, 128>>>(edge_w0 + 256*H, edge_w1, edge_w2, 1);

    // msg stage projections: PA1 = node@W0a + b0, PB1 = node@W0b
    proj_kernel<<<NBLK, 256, SMEM_SMALL>>>(node_h, msg_w0,         msg_b0, 0);
    proj_kernel<<<NBLK, 256, SMEM_SMALL>>>(node_h, msg_w0 + 128*H, nullptr, 1);
    // msg MLP on tensor cores -> g_Y2
    msg_mma_kernel<<<nsm, 512, SMEM_MMA>>>(edge_h, edge_idx, msg_b1, msg_b2);
    // k-sum + LN1 -> NODE1
    ksum_kernel<<<RES, 128>>>(node_h, ln1_g, ln1_b);
    // feed-forward + LN2 -> out_node
    ff1_kernel<<<dim3(NBLK, 4), 256, SMEM_SMALL>>>(ff_w0, ff_b0);
    ff2_kernel<<<NBLK, 256, SMEM_SMALL>>>(ff_w1, ff_b1, ln2_g, ln2_b, out_node);
    // edge stage projections from refreshed nodes
    proj_kernel<<<NBLK, 256, SMEM_SMALL>>>(out_node, edge_w0,         edge_b0, 2);
    proj_kernel<<<NBLK, 256, SMEM_SMALL>>>(out_node, edge_w0 + 128*H, nullptr, 3);
    // edge MLP on tensor cores + residual + LNe -> out_edge
    edge_mma_kernel<<<nsm, 512, SMEM_MMA>>>(edge_h, edge_idx, edge_b1, edge_b2,
                                            lne_g, lne_b, out_edge);
    (void)in_sizes; (void)n_in; (void)out_size;
}

// round 15
// speedup vs baseline: 1.0745x; 1.0745x over previous
#include <cuda_runtime.h>
#include <cuda_bf16.h>
#include <math.h>
#include <stdint.h>

// ---------------------------------------------------------------------------
// EncoderLayer R15: mma.sync m16n8k16 bf16 (fp32 acc, bf16x3 split), R12
// geometry (256 threads, 8 warps, 32x64 warp tiles) + double-buffered B
// (weight copy overlapped with epilogue) + fewer barriers (9 -> 6/7 per tile).
//   concat(h_i,h_j,e)@W0 == h_i@W0a + h_j@W0b + e@W0c ; h_j@W0b gathered.
// ---------------------------------------------------------------------------

#define RES   12000
#define KN    48
#define H     128
#define HH    (H*H)
#define TILE_FLOATS (KN*H)
#define NEDGE (RES*KN)
#define NTILES (NEDGE/128)        // 4500

typedef unsigned long long u64;
typedef unsigned int u32;

// Scratch globals (sanctioned no-alloc path)
__device__ float g_PA1[RES*H];
__device__ float g_PB1[RES*H];
__device__ float g_PA2[RES*H];
__device__ float g_PB2[RES*H];
__device__ float g_NODE1[RES*H];
__device__ float g_FFH[(size_t)RES*4*H];
__device__ float g_Y2[(size_t)NEDGE*H];                  // msg y2 scratch
#define ASZ 34816                                        // 128 rows * 272B
__device__ __align__(16) unsigned char g_WT[2][3][2*ASZ];

__device__ __forceinline__ float gelu(float x){
    return 0.5f * x * (1.0f + erff(x * 0.7071067811865475f));
}

// ---------------- packed f32x2 helpers (FFMA2 small kernels) ---------------
__device__ __forceinline__ u64 pk2(float x){
    u64 r; asm("mov.b64 %0, {%1, %1};" : "=l"(r) : "f"(x)); return r;
}
__device__ __forceinline__ u64 pk(float lo, float hi){
    u64 r; asm("mov.b64 %0, {%1, %2};" : "=l"(r) : "f"(lo), "f"(hi)); return r;
}
__device__ __forceinline__ u64 fma2(u64 a, u64 b, u64 c){
    u64 d; asm("fma.rn.f32x2 %0, %1, %2, %3;" : "=l"(d) : "l"(a), "l"(b), "l"(c)); return d;
}
__device__ __forceinline__ float2 up2(u64 v){
    float lo, hi; asm("mov.b64 {%0, %1}, %2;" : "=f"(lo), "=f"(hi) : "l"(v));
    return make_float2(lo, hi);
}

__device__ __forceinline__ void mm12(const float* __restrict__ xr,
                                     const float* __restrict__ ws,
                                     int tx, u64* __restrict__ acc){
    const float4* wp = (const float4*)ws + tx;
    #pragma unroll 1
    for (int k = 0; k < H; k += 4){
        float4 wk0 = wp[(k+0)*(H/4)];
        float4 wk1 = wp[(k+1)*(H/4)];
        float4 wk2 = wp[(k+2)*(H/4)];
        float4 wk3 = wp[(k+3)*(H/4)];
        u64 wl0 = pk(wk0.x, wk0.y), wh0 = pk(wk0.z, wk0.w);
        u64 wl1 = pk(wk1.x, wk1.y), wh1 = pk(wk1.z, wk1.w);
        u64 wl2 = pk(wk2.x, wk2.y), wh2 = pk(wk2.z, wk2.w);
        u64 wl3 = pk(wk3.x, wk3.y), wh3 = pk(wk3.z, wk3.w);
        #pragma unroll
        for (int r = 0; r < 12; r++){
            float4 xv = *(const float4*)(xr + r*H + k);
            u64* a = acc + r*2;
            u64 s;
            s = pk2(xv.x); a[0] = fma2(s, wl0, a[0]); a[1] = fma2(s, wh0, a[1]);
            s = pk2(xv.y); a[0] = fma2(s, wl1, a[0]); a[1] = fma2(s, wh1, a[1]);
            s = pk2(xv.z); a[0] = fma2(s, wl2, a[0]); a[1] = fma2(s, wh2, a[1]);
            s = pk2(xv.w); a[0] = fma2(s, wl3, a[0]); a[1] = fma2(s, wh3, a[1]);
        }
    }
}

template<int NT>
__device__ __forceinline__ void copyN(float* dst, const float* src, int tid, int nfloats){
    const float4* s = (const float4*)src; float4* d = (float4*)dst;
    #pragma unroll 4
    for (int i = tid; i < nfloats/4; i += NT) d[i] = s[i];
}

// ==================== FFMA2 kernels (proj / ff1 / ff2) =====================
__global__ void __launch_bounds__(256, 2)
proj_kernel(const float* __restrict__ src, const float* __restrict__ w,
            const float* __restrict__ bias, int sel){
    extern __shared__ float sm[];
    float* ws = sm; float* xs = sm + HH;
    int tid = threadIdx.x, tx = tid & 31, ty = tid >> 5;
    copyN<256>(ws, w, tid, HH);
    copyN<256>(xs, src + (size_t)blockIdx.x*2*TILE_FLOATS, tid, 2*TILE_FLOATS);
    __syncthreads();
    u64 acc[24];
    #pragma unroll
    for (int q = 0; q < 24; q++) acc[q] = 0ull;
    mm12(xs + ty*12*H, ws, tx, acc);
    float4 bv = make_float4(0.f,0.f,0.f,0.f);
    if (bias) bv = *(const float4*)(bias + 4*tx);
    float* outp = (sel==0) ? g_PA1 : (sel==1) ? g_PB1 : (sel==2) ? g_PA2 : g_PB2;
    int base = blockIdx.x * 96 + ty*12;
    #pragma unroll
    for (int r = 0; r < 12; r++){
        float2 v0 = up2(acc[r*2]), v1 = up2(acc[r*2+1]);
        *(float4*)(outp + (size_t)(base+r)*H + 4*tx) =
            make_float4(v0.x+bv.x, v0.y+bv.y, v1.x+bv.z, v1.y+bv.w);
    }
}

__global__ void __launch_bounds__(256, 2)
ff1_kernel(const float* __restrict__ w, const float* __restrict__ bias){
    extern __shared__ float sm[];
    float* ws = sm; float* xs = sm + HH;
    int tid = threadIdx.x, tx = tid & 31, ty = tid >> 5;
    int n0 = blockIdx.y * H;
    {
        float4* d = (float4*)ws;
        #pragma unroll 4
        for (int i = tid; i < HH/4; i += 256){
            int k = i >> 5, c = i & 31;
            d[i] = *(const float4*)(w + (size_t)k*(4*H) + n0 + 4*c);
        }
    }
    copyN<256>(xs, g_NODE1 + (size_t)blockIdx.x*2*TILE_FLOATS, tid, 2*TILE_FLOATS);
    __syncthreads();
    u64 acc[24];
    #pragma unroll
    for (int q = 0; q < 24; q++) acc[q] = 0ull;
    mm12(xs + ty*12*H, ws, tx, acc);
    float4 bv = *(const float4*)(bias + n0 + 4*tx);
    int base = blockIdx.x * 96 + ty*12;
    #pragma unroll
    for (int r = 0; r < 12; r++){
        float2 v0 = up2(acc[r*2]), v1 = up2(acc[r*2+1]);
        *(float4*)(g_FFH + (size_t)(base+r)*(4*H) + n0 + 4*tx) =
            make_float4(gelu(v0.x+bv.x), gelu(v0.y+bv.y),
                        gelu(v1.x+bv.z), gelu(v1.y+bv.w));
    }
}

__global__ void __launch_bounds__(256, 2)
ff2_kernel(const float* __restrict__ w, const float* __restrict__ bias,
           const float* __restrict__ ln2_g, const float* __restrict__ ln2_b,
           float* __restrict__ out_node){
    extern __shared__ float sm[];
    float* ws = sm; float* xs = sm + HH;
    int tid = threadIdx.x, tx = tid & 31, ty = tid >> 5;
    int base = blockIdx.x * 96;
    u64 acc[24];
    #pragma unroll
    for (int q = 0; q < 24; q++) acc[q] = 0ull;
    for (int c = 0; c < 4; c++){
        copyN<256>(ws, w + (size_t)c*H*H, tid, HH);
        {
            float4* d = (float4*)xs;
            #pragma unroll
            for (int i = tid; i < 2*TILE_FLOATS/4; i += 256){
                int m = i >> 5, cc = i & 31;
                d[i] = *(const float4*)(g_FFH + (size_t)(base+m)*(4*H) + c*H + 4*cc);
            }
        }
        __syncthreads();
        mm12(xs + ty*12*H, ws, tx, acc);
        __syncthreads();
    }
    float4 bv = *(const float4*)(bias + 4*tx);
    float4 lg = *(const float4*)(ln2_g + 4*tx);
    float4 lb = *(const float4*)(ln2_b + 4*tx);
    #pragma unroll
    for (int r = 0; r < 12; r++){
        int row = base + ty*12 + r;
        float4 a = *(const float4*)(g_NODE1 + (size_t)row*H + 4*tx);
        float2 v0 = up2(acc[r*2]), v1 = up2(acc[r*2+1]);
        float x0 = v0.x+bv.x+a.x, x1 = v0.y+bv.y+a.y;
        float x2 = v1.x+bv.z+a.z, x3 = v1.y+bv.w+a.w;
        float s = x0+x1+x2+x3, q = x0*x0+x1*x1+x2*x2+x3*x3;
        #pragma unroll
        for (int off = 16; off; off >>= 1){
            s += __shfl_xor_sync(0xffffffffu, s, off);
            q += __shfl_xor_sync(0xffffffffu, q, off);
        }
        float mean = s * (1.0f/H);
        float rstd = rsqrtf(q*(1.0f/H) - mean*mean + 1e-5f);
        *(float4*)(out_node + (size_t)row*H + 4*tx) =
            make_float4((x0-mean)*rstd*lg.x+lb.x, (x1-mean)*rstd*lg.y+lb.y,
                        (x2-mean)*rstd*lg.z+lb.z, (x3-mean)*rstd*lg.w+lb.w);
    }
}

// ===================== mma.sync machinery (base target) ====================
#define PKB 272
#define OFF_A    1024
#define OFF_B0   (OFF_A + 2*ASZ)              // 70656
#define OFF_B1   (OFF_B0 + 2*ASZ)             // 140288
#define OFF_RED  (OFF_B1 + 2*ASZ)             // 209920 (2KB)
#define OFF_BIAS (OFF_RED + 2048)             // 211968 (2KB)
#define SMEM_MMA (OFF_BIAS + 2048)            // 214016

__device__ __forceinline__ u32 smem_u32(const void* p){
    u32 a;
    asm("{ .reg .u64 t; cvta.to.shared.u64 t, %1; cvt.u32.u64 %0, t; }"
        : "=r"(a) : "l"(p));
    return a;
}
__device__ __forceinline__ void ldsm4(u32 r[4], u32 addr){
    asm volatile("ldmatrix.sync.aligned.m8n8.x4.shared.b16 {%0,%1,%2,%3}, [%4];"
        : "=r"(r[0]), "=r"(r[1]), "=r"(r[2]), "=r"(r[3]) : "r"(addr));
}
__device__ __forceinline__ void mma_bf16(float* d, const u32* a, const u32* b){
    asm volatile("mma.sync.aligned.m16n8k16.row.col.f32.bf16.bf16.f32 "
        "{%0,%1,%2,%3}, {%4,%5,%6,%7}, {%8,%9}, {%0,%1,%2,%3};"
        : "+f"(d[0]), "+f"(d[1]), "+f"(d[2]), "+f"(d[3])
        : "r"(a[0]), "r"(a[1]), "r"(a[2]), "r"(a[3]), "r"(b[0]), "r"(b[1]));
}
__device__ __forceinline__ void split2(float x, float y, u32& hi, u32& lo){
    __nv_bfloat16 hx = __float2bfloat16_rn(x), hy = __float2bfloat16_rn(y);
    float rx = x - __bfloat162float(hx), ry = y - __bfloat162float(hy);
    __nv_bfloat16 lx = __float2bfloat16_rn(rx), ly = __float2bfloat16_rn(ry);
    hi = (u32)__bfloat16_as_ushort(hx) | ((u32)__bfloat16_as_ushort(hy) << 16);
    lo = (u32)__bfloat16_as_ushort(lx) | ((u32)__bfloat16_as_ushort(ly) << 16);
}

// 3-pass split GEMM (R12 geometry): warp tile rows mw*32..+31, cols nw*64..+63
__device__ __forceinline__ void gemm3(u32 abase_, u32 bbase_, int lane, int mw, int nw,
                                      float acc[2][8][4]){
    #pragma unroll
    for (int mt = 0; mt < 2; mt++)
        #pragma unroll
        for (int nt = 0; nt < 8; nt++)
            #pragma unroll
            for (int c = 0; c < 4; c++) acc[mt][nt][c] = 0.f;
    u32 aoff = (u32)(mw*32 + (lane & 15))*PKB + (u32)((lane >> 4) * 16);
    u32 boff = (u32)(nw*64 + ((lane >> 4) << 3) + (lane & 7))*PKB
             + (u32)(((lane >> 3) & 1) * 16);
    #pragma unroll 1
    for (int pass = 0; pass < 3; pass++){
        u32 abase = abase_ + (pass==2 ? ASZ : 0) + aoff;
        u32 bbase = bbase_ + (pass==1 ? ASZ : 0) + boff;
        #pragma unroll
        for (int ks = 0; ks < 8; ks++){
            u32 kb = (u32)(ks*32);
            u32 a0[4], a1[4], b[4][4];
            ldsm4(a0, abase + kb);
            ldsm4(a1, abase + 16*PKB + kb);
            #pragma unroll
            for (int q = 0; q < 4; q++) ldsm4(b[q], bbase + q*16*PKB + kb);
            #pragma unroll
            for (int mt = 0; mt < 2; mt++)
                #pragma unroll
                for (int nt = 0; nt < 8; nt++)
                    mma_bf16(acc[mt][nt], mt ? a1 : a0, &b[nt>>1][(nt&1)*2]);
        }
    }
}

__device__ __forceinline__ void copyB(char* dst, const unsigned char* src, int tid){
    uint4* d = (uint4*)dst; const uint4* s = (const uint4*)src;
    #pragma unroll
    for (int i = tid; i < (2*ASZ)/16; i += 256) d[i] = s[i];
}

// build A hi/lo images from a 128x128 fp32 tile (256 threads)
__device__ __forceinline__ void buildA(char* Ahi, char* Alo,
                                       const float* __restrict__ src128, int tid){
    int row = tid & 127, half = tid >> 7;
    const float2* src = (const float2*)(src128 + (size_t)row*H + half*64);
    u32 base = (u32)row*PKB + (u32)half*128;
    #pragma unroll
    for (int j = 0; j < 32; j++){
        float2 v = src[j];
        u32 hi, lo; split2(v.x, v.y, hi, lo);
        *(u32*)(Ahi + base + 4*j) = hi;
        *(u32*)(Alo + base + 4*j) = lo;
    }
}

// prebuild W^T hi/lo images, padded
__global__ void prep_wt_kernel(const float* __restrict__ w0,
                               const float* __restrict__ w1,
                               const float* __restrict__ w2, int stage){
    int bx = blockIdx.x;              // 384 = 3 mats * 128 n-rows
    int mat = bx >> 7, n = bx & 127, k = threadIdx.x;
    const float* w = (mat==0) ? w0 : (mat==1) ? w1 : w2;
    float x = w[k*H + n];             // B^T[n][k] = W[k][n]
    __nv_bfloat16 h = __float2bfloat16_rn(x);
    float l = x - __bfloat162float(h);
    __nv_bfloat16 hl = __float2bfloat16_rn(l);
    u32 off = (u32)n*PKB + (u32)k*2;
    *(__nv_bfloat16*)(&g_WT[stage][mat][0]   + off) = h;
    *(__nv_bfloat16*)(&g_WT[stage][mat][ASZ] + off) = hl;
}

// ---------------------- msg stage mma kernel -------------------------------
__global__ void __launch_bounds__(256, 1)
msg_mma_kernel(const float* __restrict__ edge_h, const int* __restrict__ edge_idx,
               const float* __restrict__ b1, const float* __restrict__ b2){
    extern __shared__ char smc[];
    u32 sb = smem_u32(smc);
    char* Ahi = smc + OFF_A; char* Alo = Ahi + ASZ;
    float* sb1 = (float*)(smc + OFF_BIAS);
    float* sb2 = sb1 + 128;
    int tid = threadIdx.x, lane = tid & 31, w = tid >> 5;
    int mw = w & 3, nw = w >> 2;
    int g = lane >> 2, t2 = (lane & 3)*2;
    u32 abase = sb + OFF_A;
    if (tid < 128){ sb1[tid] = b1[tid]; sb2[tid] = b2[tid]; }
    int buf = 0;
    copyB(smc + OFF_B0, g_WT[0][0], tid);        // prime layer-0 weights

    for (int tile = blockIdx.x; tile < NTILES; tile += gridDim.x){
        buildA(Ahi, Alo, edge_h + (size_t)tile*128*H, tid);
        int rows[4], jr4[4], ir4[4];
        #pragma unroll
        for (int idx = 0; idx < 4; idx++){
            rows[idx] = mw*32 + (idx>>1)*16 + (idx&1)*8 + g;
            int gr = tile*128 + rows[idx];
            ir4[idx] = gr/48; jr4[idx] = edge_idx[gr];
        }
        __syncthreads();                          // A + primed B visible
        #pragma unroll 1
        for (int layer = 0; layer < 3; layer++){
            float acc[2][8][4];
            gemm3(abase, sb + (buf ? OFF_B1 : OFF_B0), lane, mw, nw, acc);
            __syncthreads();                      // A/B reads complete
            // overlap: load next weights into the other buffer
            copyB(smc + (buf ? OFF_B0 : OFF_B1),
                  g_WT[0][layer < 2 ? layer + 1 : 0], tid);
            buf ^= 1;
            if (layer < 2){
                #pragma unroll
                for (int mt = 0; mt < 2; mt++)
                #pragma unroll
                for (int rr = 0; rr < 2; rr++){
                    int idx = mt*2 + rr, row = rows[idx];
                    const float* pa = g_PA1 + (size_t)ir4[idx]*H;
                    const float* pb = g_PB1 + (size_t)jr4[idx]*H;
                    #pragma unroll
                    for (int nt = 0; nt < 8; nt++){
                        int col = nw*64 + nt*8 + t2;
                        float v0 = acc[mt][nt][rr*2], v1 = acc[mt][nt][rr*2+1];
                        if (layer == 0){
                            float2 a = *(const float2*)(pa + col);
                            float2 b = *(const float2*)(pb + col);
                            v0 = gelu(v0 + a.x + b.x); v1 = gelu(v1 + a.y + b.y);
                        } else {
                            v0 = gelu(v0 + sb1[col]); v1 = gelu(v1 + sb1[col+1]);
                        }
                        u32 hi, lo; split2(v0, v1, hi, lo);
                        u32 off = (u32)row*PKB + (u32)col*2;
                        *(u32*)(Ahi + off) = hi; *(u32*)(Alo + off) = lo;
                    }
                }
                __syncthreads();                  // A writes + copyB visible
            } else {
                #pragma unroll
                for (int mt = 0; mt < 2; mt++)
                #pragma unroll
                for (int rr = 0; rr < 2; rr++){
                    int idx = mt*2 + rr;
                    size_t gr = (size_t)tile*128 + rows[idx];
                    #pragma unroll
                    for (int nt = 0; nt < 8; nt++){
                        int col = nw*64 + nt*8 + t2;
                        *(float2*)(g_Y2 + gr*H + col) = make_float2(
                            acc[mt][nt][rr*2]   + sb2[col],
                            acc[mt][nt][rr*2+1] + sb2[col+1]);
                    }
                }
                // no barrier: loop-top sync covers buildA/copyB visibility
            }
        }
    }
}

// ---------------------- edge stage mma kernel ------------------------------
__global__ void __launch_bounds__(256, 1)
edge_mma_kernel(const float* __restrict__ edge_h, const int* __restrict__ edge_idx,
                const float* __restrict__ b1, const float* __restrict__ b2,
                const float* __restrict__ lne_g, const float* __restrict__ lne_b,
                float* __restrict__ out_edge){
    extern __shared__ char smc[];
    u32 sb = smem_u32(smc);
    char* Ahi = smc + OFF_A; char* Alo = Ahi + ASZ;
    float2* red = (float2*)(smc + OFF_RED);       // [row*2 + nw]
    float* sb1 = (float*)(smc + OFF_BIAS);
    float* sb2 = sb1 + 128;
    float* slg = sb2 + 128;
    float* slb = slg + 128;
    int tid = threadIdx.x, lane = tid & 31, w = tid >> 5;
    int mw = w & 3, nw = w >> 2;
    int g = lane >> 2, t2 = (lane & 3)*2;
    u32 abase = sb + OFF_A;
    if (tid < 128){ sb1[tid]=b1[tid]; sb2[tid]=b2[tid]; slg[tid]=lne_g[tid]; slb[tid]=lne_b[tid]; }
    int buf = 0;
    copyB(smc + OFF_B0, g_WT[1][0], tid);

    for (int tile = blockIdx.x; tile < NTILES; tile += gridDim.x){
        buildA(Ahi, Alo, edge_h + (size_t)tile*128*H, tid);
        int rows[4], jr4[4], ir4[4];
        #pragma unroll
        for (int idx = 0; idx < 4; idx++){
            rows[idx] = mw*32 + (idx>>1)*16 + (idx&1)*8 + g;
            int gr = tile*128 + rows[idx];
            ir4[idx] = gr/48; jr4[idx] = edge_idx[gr];
        }
        __syncthreads();
        #pragma unroll 1
        for (int layer = 0; layer < 3; layer++){
            float acc[2][8][4];
            gemm3(abase, sb + (buf ? OFF_B1 : OFF_B0), lane, mw, nw, acc);
            __syncthreads();
            copyB(smc + (buf ? OFF_B0 : OFF_B1),
                  g_WT[1][layer < 2 ? layer + 1 : 0], tid);
            buf ^= 1;
            if (layer < 2){
                #pragma unroll
                for (int mt = 0; mt < 2; mt++)
                #pragma unroll
                for (int rr = 0; rr < 2; rr++){
                    int idx = mt*2 + rr, row = rows[idx];
                    const float* pa = g_PA2 + (size_t)ir4[idx]*H;
                    const float* pb = g_PB2 + (size_t)jr4[idx]*H;
                    #pragma unroll
                    for (int nt = 0; nt < 8; nt++){
                        int col = nw*64 + nt*8 + t2;
                        float v0 = acc[mt][nt][rr*2], v1 = acc[mt][nt][rr*2+1];
                        if (layer == 0){
                            float2 a = *(const float2*)(pa + col);
                            float2 b = *(const float2*)(pb + col);
                            v0 = gelu(v0 + a.x + b.x); v1 = gelu(v1 + a.y + b.y);
                        } else {
                            v0 = gelu(v0 + sb1[col]); v1 = gelu(v1 + sb1[col+1]);
                        }
                        u32 hi, lo; split2(v0, v1, hi, lo);
                        u32 off = (u32)row*PKB + (u32)col*2;
                        *(u32*)(Ahi + off) = hi; *(u32*)(Alo + off) = lo;
                    }
                }
                __syncthreads();
            } else {
                // x = D + b2 + edge_h ; per-row LN across the 2 nw halves
                #pragma unroll
                for (int mt = 0; mt < 2; mt++)
                #pragma unroll
                for (int rr = 0; rr < 2; rr++){
                    int idx = mt*2 + rr;
                    size_t gr = (size_t)tile*128 + rows[idx];
                    const float* eh = edge_h + gr*H;
                    float s = 0.f, q = 0.f;
                    #pragma unroll
                    for (int nt = 0; nt < 8; nt++){
                        int col = nw*64 + nt*8 + t2;
                        float2 e = *(const float2*)(eh + col);
                        float v0 = acc[mt][nt][rr*2]   + sb2[col]   + e.x;
                        float v1 = acc[mt][nt][rr*2+1] + sb2[col+1] + e.y;
                        acc[mt][nt][rr*2] = v0; acc[mt][nt][rr*2+1] = v1;
                        s += v0 + v1; q += v0*v0 + v1*v1;
                    }
                    s += __shfl_xor_sync(0xffffffffu, s, 1);
                    q += __shfl_xor_sync(0xffffffffu, q, 1);
                    s += __shfl_xor_sync(0xffffffffu, s, 2);
                    q += __shfl_xor_sync(0xffffffffu, q, 2);
                    if ((lane & 3) == 0) red[rows[idx]*2 + nw] = make_float2(s, q);
                }
                __syncthreads();
                #pragma unroll
                for (int mt = 0; mt < 2; mt++)
                #pragma unroll
                for (int rr = 0; rr < 2; rr++){
                    int idx = mt*2 + rr;
                    size_t gr = (size_t)tile*128 + rows[idx];
                    float2 r0 = red[rows[idx]*2], r1 = red[rows[idx]*2 + 1];
                    float mean = (r0.x + r1.x) * (1.0f/H);
                    float var  = (r0.y + r1.y) * (1.0f/H) - mean*mean;
                    float rstd = rsqrtf(var + 1e-5f);
                    #pragma unroll
                    for (int nt = 0; nt < 8; nt++){
                        int col = nw*64 + nt*8 + t2;
                        float v0 = acc[mt][nt][rr*2], v1 = acc[mt][nt][rr*2+1];
                        *(float2*)(out_edge + gr*H + col) = make_float2(
                            (v0-mean)*rstd*slg[col]   + slb[col],
                            (v1-mean)*rstd*slg[col+1] + slb[col+1]);
                    }
                }
                // loop-top sync protects red reuse + buildA
            }
        }
    }
}

// ---------------- k-sum + LN1 over g_Y2 -> NODE1 ---------------------------
__global__ void __launch_bounds__(128)
ksum_kernel(const float* __restrict__ node_h, const float* __restrict__ ln1_g,
            const float* __restrict__ ln1_b){
    __shared__ float sv[130];
    int i = blockIdx.x, c = threadIdx.x;
    const float* y = g_Y2 + (size_t)i*KN*H + c;
    float s = 0.f;
    #pragma unroll 8
    for (int k = 0; k < KN; k++) s += y[(size_t)k*H];
    float v = node_h[(size_t)i*H + c] + s;
    sv[c] = v;
    __syncthreads();
    if (c < 32){
        float a = 0.f, q = 0.f;
        #pragma unroll
        for (int g2 = 0; g2 < 4; g2++){ float x = sv[c + 32*g2]; a += x; q += x*x; }
        #pragma unroll
        for (int off = 16; off; off >>= 1){
            a += __shfl_xor_sync(0xffffffffu, a, off);
            q += __shfl_xor_sync(0xffffffffu, q, off);
        }
        if (c == 0){
            float mean = a * (1.0f/H);
            sv[128] = mean;
            sv[129] = rsqrtf(q*(1.0f/H) - mean*mean + 1e-5f);
        }
    }
    __syncthreads();
    g_NODE1[(size_t)i*H + c] = (v - sv[128]) * sv[129] * ln1_g[c] + ln1_b[c];
}

// ---------------------------------------------------------------------------
extern "C" void kernel_launch(void* const* d_in, const int* in_sizes, int n_in,
                              void* d_out, int out_size){
    const float* node_h  = (const float*)d_in[0];
    const float* edge_h  = (const float*)d_in[1];
    const float* msg_w0  = (const float*)d_in[2];
    const float* msg_b0  = (const float*)d_in[3];
    const float* msg_w1  = (const float*)d_in[4];
    const float* msg_b1  = (const float*)d_in[5];
    const float* msg_w2  = (const float*)d_in[6];
    const float* msg_b2  = (const float*)d_in[7];
    const float* ff_w0   = (const float*)d_in[8];
    const float* ff_b0   = (const float*)d_in[9];
    const float* ff_w1   = (const float*)d_in[10];
    const float* ff_b1   = (const float*)d_in[11];
    const float* edge_w0 = (const float*)d_in[12];
    const float* edge_b0 = (const float*)d_in[13];
    const float* edge_w1 = (const float*)d_in[14];
    const float* edge_b1 = (const float*)d_in[15];
    const float* edge_w2 = (const float*)d_in[16];
    const float* edge_b2 = (const float*)d_in[17];
    const float* ln1_g   = (const float*)d_in[18];
    const float* ln1_b   = (const float*)d_in[19];
    const float* ln2_g   = (const float*)d_in[20];
    const float* ln2_b   = (const float*)d_in[21];
    const float* lne_g   = (const float*)d_in[22];
    const float* lne_b   = (const float*)d_in[23];
    const int*   edge_idx= (const int*)  d_in[24];

    float* out_node = (float*)d_out;
    float* out_edge = out_node + (size_t)RES*H;

    const int SMEM_SMALL = (HH + 2*TILE_FLOATS) * 4;   // 114688
    cudaFuncSetAttribute(proj_kernel, cudaFuncAttributeMaxDynamicSharedMemorySize, SMEM_SMALL);
    cudaFuncSetAttribute(ff1_kernel,  cudaFuncAttributeMaxDynamicSharedMemorySize, SMEM_SMALL);
    cudaFuncSetAttribute(ff2_kernel,  cudaFuncAttributeMaxDynamicSharedMemorySize, SMEM_SMALL);
    cudaFuncSetAttribute(msg_mma_kernel,  cudaFuncAttributeMaxDynamicSharedMemorySize, SMEM_MMA);
    cudaFuncSetAttribute(edge_mma_kernel, cudaFuncAttributeMaxDynamicSharedMemorySize, SMEM_MMA);

    int dev = 0, nsm = 148;
    if (cudaGetDevice(&dev) == cudaSuccess){
        int v = 0;
        if (cudaDeviceGetAttribute(&v, cudaDevAttrMultiProcessorCount, dev) == cudaSuccess && v > 0)
            nsm = v;
    }

    const int NBLK = RES / 96;   // 125

    // W^T image prep (both stages)
    prep_wt_kernel<<<384, 128>>>(msg_w0 + 256*H,  msg_w1,  msg_w2,  0);
    prep_wt_kernel<<<384, 128>>>(edge_w0 + 256*H, edge_w1, edge_w2, 1);

    // msg stage projections: PA1 = node@W0a + b0, PB1 = node@W0b
    proj_kernel<<<NBLK, 256, SMEM_SMALL>>>(node_h, msg_w0,         msg_b0, 0);
    proj_kernel<<<NBLK, 256, SMEM_SMALL>>>(node_h, msg_w0 + 128*H, nullptr, 1);
    // msg MLP on tensor cores -> g_Y2
    msg_mma_kernel<<<nsm, 256, SMEM_MMA>>>(edge_h, edge_idx, msg_b1, msg_b2);
    // k-sum + LN1 -> NODE1
    ksum_kernel<<<RES, 128>>>(node_h, ln1_g, ln1_b);
    // feed-forward + LN2 -> out_node
    ff1_kernel<<<dim3(NBLK, 4), 256, SMEM_SMALL>>>(ff_w0, ff_b0);
    ff2_kernel<<<NBLK, 256, SMEM_SMALL>>>(ff_w1, ff_b1, ln2_g, ln2_b, out_node);
    // edge stage projections from refreshed nodes
    proj_kernel<<<NBLK, 256, SMEM_SMALL>>>(out_node, edge_w0,         edge_b0, 2);
    proj_kernel<<<NBLK, 256, SMEM_SMALL>>>(out_node, edge_w0 + 128*H, nullptr, 3);
    // edge MLP on tensor cores + residual + LNe -> out_edge
    edge_mma_kernel<<<nsm, 256, SMEM_MMA>>>(edge_h, edge_idx, edge_b1, edge_b2,
                                            lne_g, lne_b, out_edge);
    (void)in_sizes; (void)n_in; (void)out_size;
}

// round 16
// speedup vs baseline: 1.1105x; 1.0335x over previous
#include <cuda_runtime.h>
#include <cuda_bf16.h>
#include <math.h>
#include <stdint.h>

// ---------------------------------------------------------------------------
// EncoderLayer R16: mma.sync m16n8k16 bf16 (fp32 acc, bf16x3 split), R12
// geometry (256 threads, 8 warps, 32x64 warp tiles) + TRUE async double-
// buffered B via cp.async (R15's sync copy blocked the issuing thread).
//   concat(h_i,h_j,e)@W0 == h_i@W0a + h_j@W0b + e@W0c ; h_j@W0b gathered.
// Buffer schedule per tile (buf flips each tile): L0,L2 read buf; L1 reads
// buf^1. Prefetch B1->buf^1 at tile start, B2->buf after L0 gemm, B0(next)
// ->buf^1 after L1 gemm. cp.async.wait_group 1 before each pre-gemm barrier.
// ---------------------------------------------------------------------------

#define RES   12000
#define KN    48
#define H     128
#define HH    (H*H)
#define TILE_FLOATS (KN*H)
#define NEDGE (RES*KN)
#define NTILES (NEDGE/128)        // 4500

typedef unsigned long long u64;
typedef unsigned int u32;

// Scratch globals (sanctioned no-alloc path)
__device__ float g_PA1[RES*H];
__device__ float g_PB1[RES*H];
__device__ float g_PA2[RES*H];
__device__ float g_PB2[RES*H];
__device__ float g_NODE1[RES*H];
__device__ float g_FFH[(size_t)RES*4*H];
__device__ float g_Y2[(size_t)NEDGE*H];                  // msg y2 scratch
#define ASZ 34816                                        // 128 rows * 272B
__device__ __align__(16) unsigned char g_WT[2][3][2*ASZ];

__device__ __forceinline__ float gelu(float x){
    return 0.5f * x * (1.0f + erff(x * 0.7071067811865475f));
}

// ---------------- packed f32x2 helpers (FFMA2 small kernels) ---------------
__device__ __forceinline__ u64 pk2(float x){
    u64 r; asm("mov.b64 %0, {%1, %1};" : "=l"(r) : "f"(x)); return r;
}
__device__ __forceinline__ u64 pk(float lo, float hi){
    u64 r; asm("mov.b64 %0, {%1, %2};" : "=l"(r) : "f"(lo), "f"(hi)); return r;
}
__device__ __forceinline__ u64 fma2(u64 a, u64 b, u64 c){
    u64 d; asm("fma.rn.f32x2 %0, %1, %2, %3;" : "=l"(d) : "l"(a), "l"(b), "l"(c)); return d;
}
__device__ __forceinline__ float2 up2(u64 v){
    float lo, hi; asm("mov.b64 {%0, %1}, %2;" : "=f"(lo), "=f"(hi) : "l"(v));
    return make_float2(lo, hi);
}

__device__ __forceinline__ void mm12(const float* __restrict__ xr,
                                     const float* __restrict__ ws,
                                     int tx, u64* __restrict__ acc){
    const float4* wp = (const float4*)ws + tx;
    #pragma unroll 1
    for (int k = 0; k < H; k += 4){
        float4 wk0 = wp[(k+0)*(H/4)];
        float4 wk1 = wp[(k+1)*(H/4)];
        float4 wk2 = wp[(k+2)*(H/4)];
        float4 wk3 = wp[(k+3)*(H/4)];
        u64 wl0 = pk(wk0.x, wk0.y), wh0 = pk(wk0.z, wk0.w);
        u64 wl1 = pk(wk1.x, wk1.y), wh1 = pk(wk1.z, wk1.w);
        u64 wl2 = pk(wk2.x, wk2.y), wh2 = pk(wk2.z, wk2.w);
        u64 wl3 = pk(wk3.x, wk3.y), wh3 = pk(wk3.z, wk3.w);
        #pragma unroll
        for (int r = 0; r < 12; r++){
            float4 xv = *(const float4*)(xr + r*H + k);
            u64* a = acc + r*2;
            u64 s;
            s = pk2(xv.x); a[0] = fma2(s, wl0, a[0]); a[1] = fma2(s, wh0, a[1]);
            s = pk2(xv.y); a[0] = fma2(s, wl1, a[0]); a[1] = fma2(s, wh1, a[1]);
            s = pk2(xv.z); a[0] = fma2(s, wl2, a[0]); a[1] = fma2(s, wh2, a[1]);
            s = pk2(xv.w); a[0] = fma2(s, wl3, a[0]); a[1] = fma2(s, wh3, a[1]);
        }
    }
}

template<int NT>
__device__ __forceinline__ void copyN(float* dst, const float* src, int tid, int nfloats){
    const float4* s = (const float4*)src; float4* d = (float4*)dst;
    #pragma unroll 4
    for (int i = tid; i < nfloats/4; i += NT) d[i] = s[i];
}

// ==================== FFMA2 kernels (proj / ff1 / ff2) =====================
__global__ void __launch_bounds__(256, 2)
proj_kernel(const float* __restrict__ src, const float* __restrict__ w,
            const float* __restrict__ bias, int sel){
    extern __shared__ float sm[];
    float* ws = sm; float* xs = sm + HH;
    int tid = threadIdx.x, tx = tid & 31, ty = tid >> 5;
    copyN<256>(ws, w, tid, HH);
    copyN<256>(xs, src + (size_t)blockIdx.x*2*TILE_FLOATS, tid, 2*TILE_FLOATS);
    __syncthreads();
    u64 acc[24];
    #pragma unroll
    for (int q = 0; q < 24; q++) acc[q] = 0ull;
    mm12(xs + ty*12*H, ws, tx, acc);
    float4 bv = make_float4(0.f,0.f,0.f,0.f);
    if (bias) bv = *(const float4*)(bias + 4*tx);
    float* outp = (sel==0) ? g_PA1 : (sel==1) ? g_PB1 : (sel==2) ? g_PA2 : g_PB2;
    int base = blockIdx.x * 96 + ty*12;
    #pragma unroll
    for (int r = 0; r < 12; r++){
        float2 v0 = up2(acc[r*2]), v1 = up2(acc[r*2+1]);
        *(float4*)(outp + (size_t)(base+r)*H + 4*tx) =
            make_float4(v0.x+bv.x, v0.y+bv.y, v1.x+bv.z, v1.y+bv.w);
    }
}

__global__ void __launch_bounds__(256, 2)
ff1_kernel(const float* __restrict__ w, const float* __restrict__ bias){
    extern __shared__ float sm[];
    float* ws = sm; float* xs = sm + HH;
    int tid = threadIdx.x, tx = tid & 31, ty = tid >> 5;
    int n0 = blockIdx.y * H;
    {
        float4* d = (float4*)ws;
        #pragma unroll 4
        for (int i = tid; i < HH/4; i += 256){
            int k = i >> 5, c = i & 31;
            d[i] = *(const float4*)(w + (size_t)k*(4*H) + n0 + 4*c);
        }
    }
    copyN<256>(xs, g_NODE1 + (size_t)blockIdx.x*2*TILE_FLOATS, tid, 2*TILE_FLOATS);
    __syncthreads();
    u64 acc[24];
    #pragma unroll
    for (int q = 0; q < 24; q++) acc[q] = 0ull;
    mm12(xs + ty*12*H, ws, tx, acc);
    float4 bv = *(const float4*)(bias + n0 + 4*tx);
    int base = blockIdx.x * 96 + ty*12;
    #pragma unroll
    for (int r = 0; r < 12; r++){
        float2 v0 = up2(acc[r*2]), v1 = up2(acc[r*2+1]);
        *(float4*)(g_FFH + (size_t)(base+r)*(4*H) + n0 + 4*tx) =
            make_float4(gelu(v0.x+bv.x), gelu(v0.y+bv.y),
                        gelu(v1.x+bv.z), gelu(v1.y+bv.w));
    }
}

__global__ void __launch_bounds__(256, 2)
ff2_kernel(const float* __restrict__ w, const float* __restrict__ bias,
           const float* __restrict__ ln2_g, const float* __restrict__ ln2_b,
           float* __restrict__ out_node){
    extern __shared__ float sm[];
    float* ws = sm; float* xs = sm + HH;
    int tid = threadIdx.x, tx = tid & 31, ty = tid >> 5;
    int base = blockIdx.x * 96;
    u64 acc[24];
    #pragma unroll
    for (int q = 0; q < 24; q++) acc[q] = 0ull;
    for (int c = 0; c < 4; c++){
        copyN<256>(ws, w + (size_t)c*H*H, tid, HH);
        {
            float4* d = (float4*)xs;
            #pragma unroll
            for (int i = tid; i < 2*TILE_FLOATS/4; i += 256){
                int m = i >> 5, cc = i & 31;
                d[i] = *(const float4*)(g_FFH + (size_t)(base+m)*(4*H) + c*H + 4*cc);
            }
        }
        __syncthreads();
        mm12(xs + ty*12*H, ws, tx, acc);
        __syncthreads();
    }
    float4 bv = *(const float4*)(bias + 4*tx);
    float4 lg = *(const float4*)(ln2_g + 4*tx);
    float4 lb = *(const float4*)(ln2_b + 4*tx);
    #pragma unroll
    for (int r = 0; r < 12; r++){
        int row = base + ty*12 + r;
        float4 a = *(const float4*)(g_NODE1 + (size_t)row*H + 4*tx);
        float2 v0 = up2(acc[r*2]), v1 = up2(acc[r*2+1]);
        float x0 = v0.x+bv.x+a.x, x1 = v0.y+bv.y+a.y;
        float x2 = v1.x+bv.z+a.z, x3 = v1.y+bv.w+a.w;
        float s = x0+x1+x2+x3, q = x0*x0+x1*x1+x2*x2+x3*x3;
        #pragma unroll
        for (int off = 16; off; off >>= 1){
            s += __shfl_xor_sync(0xffffffffu, s, off);
            q += __shfl_xor_sync(0xffffffffu, q, off);
        }
        float mean = s * (1.0f/H);
        float rstd = rsqrtf(q*(1.0f/H) - mean*mean + 1e-5f);
        *(float4*)(out_node + (size_t)row*H + 4*tx) =
            make_float4((x0-mean)*rstd*lg.x+lb.x, (x1-mean)*rstd*lg.y+lb.y,
                        (x2-mean)*rstd*lg.z+lb.z, (x3-mean)*rstd*lg.w+lb.w);
    }
}

// ===================== mma.sync machinery (base target) ====================
#define PKB 272
#define OFF_A    1024
#define OFF_B0   (OFF_A + 2*ASZ)              // 70656
#define OFF_B1   (OFF_B0 + 2*ASZ)             // 140288
#define OFF_RED  (OFF_B1 + 2*ASZ)             // 209920 (2KB)
#define OFF_BIAS (OFF_RED + 2048)             // 211968 (2KB)
#define SMEM_MMA (OFF_BIAS + 2048)            // 214016

__device__ __forceinline__ u32 smem_u32(const void* p){
    u32 a;
    asm("{ .reg .u64 t; cvta.to.shared.u64 t, %1; cvt.u32.u64 %0, t; }"
        : "=r"(a) : "l"(p));
    return a;
}
__device__ __forceinline__ void ldsm4(u32 r[4], u32 addr){
    asm volatile("ldmatrix.sync.aligned.m8n8.x4.shared.b16 {%0,%1,%2,%3}, [%4];"
        : "=r"(r[0]), "=r"(r[1]), "=r"(r[2]), "=r"(r[3]) : "r"(addr));
}
__device__ __forceinline__ void mma_bf16(float* d, const u32* a, const u32* b){
    asm volatile("mma.sync.aligned.m16n8k16.row.col.f32.bf16.bf16.f32 "
        "{%0,%1,%2,%3}, {%4,%5,%6,%7}, {%8,%9}, {%0,%1,%2,%3};"
        : "+f"(d[0]), "+f"(d[1]), "+f"(d[2]), "+f"(d[3])
        : "r"(a[0]), "r"(a[1]), "r"(a[2]), "r"(a[3]), "r"(b[0]), "r"(b[1]));
}
__device__ __forceinline__ void split2(float x, float y, u32& hi, u32& lo){
    __nv_bfloat16 hx = __float2bfloat16_rn(x), hy = __float2bfloat16_rn(y);
    float rx = x - __bfloat162float(hx), ry = y - __bfloat162float(hy);
    __nv_bfloat16 lx = __float2bfloat16_rn(rx), ly = __float2bfloat16_rn(ry);
    hi = (u32)__bfloat16_as_ushort(hx) | ((u32)__bfloat16_as_ushort(hy) << 16);
    lo = (u32)__bfloat16_as_ushort(lx) | ((u32)__bfloat16_as_ushort(ly) << 16);
}

// 3-pass split GEMM (R12 geometry): warp tile rows mw*32..+31, cols nw*64..+63
__device__ __forceinline__ void gemm3(u32 abase_, u32 bbase_, int lane, int mw, int nw,
                                      float acc[2][8][4]){
    #pragma unroll
    for (int mt = 0; mt < 2; mt++)
        #pragma unroll
        for (int nt = 0; nt < 8; nt++)
            #pragma unroll
            for (int c = 0; c < 4; c++) acc[mt][nt][c] = 0.f;
    u32 aoff = (u32)(mw*32 + (lane & 15))*PKB + (u32)((lane >> 4) * 16);
    u32 boff = (u32)(nw*64 + ((lane >> 4) << 3) + (lane & 7))*PKB
             + (u32)(((lane >> 3) & 1) * 16);
    #pragma unroll 1
    for (int pass = 0; pass < 3; pass++){
        u32 abase = abase_ + (pass==2 ? ASZ : 0) + aoff;
        u32 bbase = bbase_ + (pass==1 ? ASZ : 0) + boff;
        #pragma unroll
        for (int ks = 0; ks < 8; ks++){
            u32 kb = (u32)(ks*32);
            u32 a0[4], a1[4], b[4][4];
            ldsm4(a0, abase + kb);
            ldsm4(a1, abase + 16*PKB + kb);
            #pragma unroll
            for (int q = 0; q < 4; q++) ldsm4(b[q], bbase + q*16*PKB + kb);
            #pragma unroll
            for (int mt = 0; mt < 2; mt++)
                #pragma unroll
                for (int nt = 0; nt < 8; nt++)
                    mma_bf16(acc[mt][nt], mt ? a1 : a0, &b[nt>>1][(nt&1)*2]);
        }
    }
}

// truly asynchronous 68KB weight copy (cp.async, one commit group)
__device__ __forceinline__ void copyB_async(u32 dst, const unsigned char* src, int tid){
    #pragma unroll
    for (int i = tid; i < (2*ASZ)/16; i += 256){
        asm volatile("cp.async.cg.shared.global [%0], [%1], 16;"
            :: "r"(dst + (u32)i*16), "l"(src + (size_t)i*16));
    }
    asm volatile("cp.async.commit_group;" ::: "memory");
}
#define CP_WAIT1() asm volatile("cp.async.wait_group 1;" ::: "memory")

// build A hi/lo images from a 128x128 fp32 tile (256 threads)
__device__ __forceinline__ void buildA(char* Ahi, char* Alo,
                                       const float* __restrict__ src128, int tid){
    int row = tid & 127, half = tid >> 7;
    const float2* src = (const float2*)(src128 + (size_t)row*H + half*64);
    u32 base = (u32)row*PKB + (u32)half*128;
    #pragma unroll
    for (int j = 0; j < 32; j++){
        float2 v = src[j];
        u32 hi, lo; split2(v.x, v.y, hi, lo);
        *(u32*)(Ahi + base + 4*j) = hi;
        *(u32*)(Alo + base + 4*j) = lo;
    }
}

// prebuild W^T hi/lo images, padded
__global__ void prep_wt_kernel(const float* __restrict__ w0,
                               const float* __restrict__ w1,
                               const float* __restrict__ w2, int stage){
    int bx = blockIdx.x;              // 384 = 3 mats * 128 n-rows
    int mat = bx >> 7, n = bx & 127, k = threadIdx.x;
    const float* w = (mat==0) ? w0 : (mat==1) ? w1 : w2;
    float x = w[k*H + n];             // B^T[n][k] = W[k][n]
    __nv_bfloat16 h = __float2bfloat16_rn(x);
    float l = x - __bfloat162float(h);
    __nv_bfloat16 hl = __float2bfloat16_rn(l);
    u32 off = (u32)n*PKB + (u32)k*2;
    *(__nv_bfloat16*)(&g_WT[stage][mat][0]   + off) = h;
    *(__nv_bfloat16*)(&g_WT[stage][mat][ASZ] + off) = hl;
}

// ---------------------- msg stage mma kernel -------------------------------
__global__ void __launch_bounds__(256, 1)
msg_mma_kernel(const float* __restrict__ edge_h, const int* __restrict__ edge_idx,
               const float* __restrict__ b1, const float* __restrict__ b2){
    extern __shared__ char smc[];
    u32 sb = smem_u32(smc);
    char* Ahi = smc + OFF_A; char* Alo = Ahi + ASZ;
    float* sb1 = (float*)(smc + OFF_BIAS);
    float* sb2 = sb1 + 128;
    int tid = threadIdx.x, lane = tid & 31, w = tid >> 5;
    int mw = w & 3, nw = w >> 2;
    int g = lane >> 2, t2 = (lane & 3)*2;
    u32 abase = sb + OFF_A;
    if (tid < 128){ sb1[tid] = b1[tid]; sb2[tid] = b2[tid]; }
    int buf = 0;                                  // L0/L2 buffer index
    copyB_async(sb + OFF_B0, g_WT[0][0], tid);    // prime B0 -> buf0

    for (int tile = blockIdx.x; tile < NTILES; tile += gridDim.x){
        buildA(Ahi, Alo, edge_h + (size_t)tile*128*H, tid);
        // prefetch B1 into buf^1
        copyB_async(sb + (buf ? OFF_B0 : OFF_B1), g_WT[0][1], tid);
        int rows[4], jr4[4], ir4[4];
        #pragma unroll
        for (int idx = 0; idx < 4; idx++){
            rows[idx] = mw*32 + (idx>>1)*16 + (idx&1)*8 + g;
            int gr = tile*128 + rows[idx];
            ir4[idx] = gr/48; jr4[idx] = edge_idx[gr];
        }
        #pragma unroll 1
        for (int layer = 0; layer < 3; layer++){
            CP_WAIT1();
            __syncthreads();                      // A + this layer's B ready
            u32 bb = sb + (((layer == 1) ? (buf ^ 1) : buf) ? OFF_B1 : OFF_B0);
            float acc[2][8][4];
            gemm3(abase, bb, lane, mw, nw, acc);
            __syncthreads();                      // A/B reads complete
            if (layer == 0)       // B2 -> buf (L0's buffer, now free)
                copyB_async(sb + (buf ? OFF_B1 : OFF_B0), g_WT[0][2], tid);
            else if (layer == 1)  // B0(next tile) -> buf^1 (L1's buffer, free)
                copyB_async(sb + (buf ? OFF_B0 : OFF_B1), g_WT[0][0], tid);
            if (layer < 2){
                #pragma unroll
                for (int mt = 0; mt < 2; mt++)
                #pragma unroll
                for (int rr = 0; rr < 2; rr++){
                    int idx = mt*2 + rr, row = rows[idx];
                    const float* pa = g_PA1 + (size_t)ir4[idx]*H;
                    const float* pb = g_PB1 + (size_t)jr4[idx]*H;
                    #pragma unroll
                    for (int nt = 0; nt < 8; nt++){
                        int col = nw*64 + nt*8 + t2;
                        float v0 = acc[mt][nt][rr*2], v1 = acc[mt][nt][rr*2+1];
                        if (layer == 0){
                            float2 a = *(const float2*)(pa + col);
                            float2 b = *(const float2*)(pb + col);
                            v0 = gelu(v0 + a.x + b.x); v1 = gelu(v1 + a.y + b.y);
                        } else {
                            v0 = gelu(v0 + sb1[col]); v1 = gelu(v1 + sb1[col+1]);
                        }
                        u32 hi, lo; split2(v0, v1, hi, lo);
                        u32 off = (u32)row*PKB + (u32)col*2;
                        *(u32*)(Ahi + off) = hi; *(u32*)(Alo + off) = lo;
                    }
                }
            } else {
                #pragma unroll
                for (int mt = 0; mt < 2; mt++)
                #pragma unroll
                for (int rr = 0; rr < 2; rr++){
                    int idx = mt*2 + rr;
                    size_t gr = (size_t)tile*128 + rows[idx];
                    #pragma unroll
                    for (int nt = 0; nt < 8; nt++){
                        int col = nw*64 + nt*8 + t2;
                        *(float2*)(g_Y2 + gr*H + col) = make_float2(
                            acc[mt][nt][rr*2]   + sb2[col],
                            acc[mt][nt][rr*2+1] + sb2[col+1]);
                    }
                }
            }
        }
        buf ^= 1;                                 // next tile: L0 reads B0(next)
    }
}

// ---------------------- edge stage mma kernel ------------------------------
__global__ void __launch_bounds__(256, 1)
edge_mma_kernel(const float* __restrict__ edge_h, const int* __restrict__ edge_idx,
                const float* __restrict__ b1, const float* __restrict__ b2,
                const float* __restrict__ lne_g, const float* __restrict__ lne_b,
                float* __restrict__ out_edge){
    extern __shared__ char smc[];
    u32 sb = smem_u32(smc);
    char* Ahi = smc + OFF_A; char* Alo = Ahi + ASZ;
    float2* red = (float2*)(smc + OFF_RED);       // [row*2 + nw]
    float* sb1 = (float*)(smc + OFF_BIAS);
    float* sb2 = sb1 + 128;
    float* slg = sb2 + 128;
    float* slb = slg + 128;
    int tid = threadIdx.x, lane = tid & 31, w = tid >> 5;
    int mw = w & 3, nw = w >> 2;
    int g = lane >> 2, t2 = (lane & 3)*2;
    u32 abase = sb + OFF_A;
    if (tid < 128){ sb1[tid]=b1[tid]; sb2[tid]=b2[tid]; slg[tid]=lne_g[tid]; slb[tid]=lne_b[tid]; }
    int buf = 0;
    copyB_async(sb + OFF_B0, g_WT[1][0], tid);

    for (int tile = blockIdx.x; tile < NTILES; tile += gridDim.x){
        buildA(Ahi, Alo, edge_h + (size_t)tile*128*H, tid);
        copyB_async(sb + (buf ? OFF_B0 : OFF_B1), g_WT[1][1], tid);
        int rows[4], jr4[4], ir4[4];
        #pragma unroll
        for (int idx = 0; idx < 4; idx++){
            rows[idx] = mw*32 + (idx>>1)*16 + (idx&1)*8 + g;
            int gr = tile*128 + rows[idx];
            ir4[idx] = gr/48; jr4[idx] = edge_idx[gr];
        }
        #pragma unroll 1
        for (int layer = 0; layer < 3; layer++){
            CP_WAIT1();
            __syncthreads();
            u32 bb = sb + (((layer == 1) ? (buf ^ 1) : buf) ? OFF_B1 : OFF_B0);
            float acc[2][8][4];
            gemm3(abase, bb, lane, mw, nw, acc);
            __syncthreads();
            if (layer == 0)
                copyB_async(sb + (buf ? OFF_B1 : OFF_B0), g_WT[1][2], tid);
            else if (layer == 1)
                copyB_async(sb + (buf ? OFF_B0 : OFF_B1), g_WT[1][0], tid);
            if (layer < 2){
                #pragma unroll
                for (int mt = 0; mt < 2; mt++)
                #pragma unroll
                for (int rr = 0; rr < 2; rr++){
                    int idx = mt*2 + rr, row = rows[idx];
                    const float* pa = g_PA2 + (size_t)ir4[idx]*H;
                    const float* pb = g_PB2 + (size_t)jr4[idx]*H;
                    #pragma unroll
                    for (int nt = 0; nt < 8; nt++){
                        int col = nw*64 + nt*8 + t2;
                        float v0 = acc[mt][nt][rr*2], v1 = acc[mt][nt][rr*2+1];
                        if (layer == 0){
                            float2 a = *(const float2*)(pa + col);
                            float2 b = *(const float2*)(pb + col);
                            v0 = gelu(v0 + a.x + b.x); v1 = gelu(v1 + a.y + b.y);
                        } else {
                            v0 = gelu(v0 + sb1[col]); v1 = gelu(v1 + sb1[col+1]);
                        }
                        u32 hi, lo; split2(v0, v1, hi, lo);
                        u32 off = (u32)row*PKB + (u32)col*2;
                        *(u32*)(Ahi + off) = hi; *(u32*)(Alo + off) = lo;
                    }
                }
            } else {
                // x = D + b2 + edge_h ; per-row LN across the 2 nw halves
                #pragma unroll
                for (int mt = 0; mt < 2; mt++)
                #pragma unroll
                for (int rr = 0; rr < 2; rr++){
                    int idx = mt*2 + rr;
                    size_t gr = (size_t)tile*128 + rows[idx];
                    const float* eh = edge_h + gr*H;
                    float s = 0.f, q = 0.f;
                    #pragma unroll
                    for (int nt = 0; nt < 8; nt++){
                        int col = nw*64 + nt*8 + t2;
                        float2 e = *(const float2*)(eh + col);
                        float v0 = acc[mt][nt][rr*2]   + sb2[col]   + e.x;
                        float v1 = acc[mt][nt][rr*2+1] + sb2[col+1] + e.y;
                        acc[mt][nt][rr*2] = v0; acc[mt][nt][rr*2+1] = v1;
                        s += v0 + v1; q += v0*v0 + v1*v1;
                    }
                    s += __shfl_xor_sync(0xffffffffu, s, 1);
                    q += __shfl_xor_sync(0xffffffffu, q, 1);
                    s += __shfl_xor_sync(0xffffffffu, s, 2);
                    q += __shfl_xor_sync(0xffffffffu, q, 2);
                    if ((lane & 3) == 0) red[rows[idx]*2 + nw] = make_float2(s, q);
                }
                __syncthreads();
                #pragma unroll
                for (int mt = 0; mt < 2; mt++)
                #pragma unroll
                for (int rr = 0; rr < 2; rr++){
                    int idx = mt*2 + rr;
                    size_t gr = (size_t)tile*128 + rows[idx];
                    float2 r0 = red[rows[idx]*2], r1 = red[rows[idx]*2 + 1];
                    float mean = (r0.x + r1.x) * (1.0f/H);
                    float var  = (r0.y + r1.y) * (1.0f/H) - mean*mean;
                    float rstd = rsqrtf(var + 1e-5f);
                    #pragma unroll
                    for (int nt = 0; nt < 8; nt++){
                        int col = nw*64 + nt*8 + t2;
                        float v0 = acc[mt][nt][rr*2], v1 = acc[mt][nt][rr*2+1];
                        *(float2*)(out_edge + gr*H + col) = make_float2(
                            (v0-mean)*rstd*slg[col]   + slb[col],
                            (v1-mean)*rstd*slg[col+1] + slb[col+1]);
                    }
                }
            }
        }
        buf ^= 1;
    }
}

// ---------------- k-sum + LN1 over g_Y2 -> NODE1 ---------------------------
__global__ void __launch_bounds__(128)
ksum_kernel(const float* __restrict__ node_h, const float* __restrict__ ln1_g,
            const float* __restrict__ ln1_b){
    __shared__ float sv[130];
    int i = blockIdx.x, c = threadIdx.x;
    const float* y = g_Y2 + (size_t)i*KN*H + c;
    float s = 0.f;
    #pragma unroll 8
    for (int k = 0; k < KN; k++) s += y[(size_t)k*H];
    float v = node_h[(size_t)i*H + c] + s;
    sv[c] = v;
    __syncthreads();
    if (c < 32){
        float a = 0.f, q = 0.f;
        #pragma unroll
        for (int g2 = 0; g2 < 4; g2++){ float x = sv[c + 32*g2]; a += x; q += x*x; }
        #pragma unroll
        for (int off = 16; off; off >>= 1){
            a += __shfl_xor_sync(0xffffffffu, a, off);
            q += __shfl_xor_sync(0xffffffffu, q, off);
        }
        if (c == 0){
            float mean = a * (1.0f/H);
            sv[128] = mean;
            sv[129] = rsqrtf(q*(1.0f/H) - mean*mean + 1e-5f);
        }
    }
    __syncthreads();
    g_NODE1[(size_t)i*H + c] = (v - sv[128]) * sv[129] * ln1_g[c] + ln1_b[c];
}

// ---------------------------------------------------------------------------
extern "C" void kernel_launch(void* const* d_in, const int* in_sizes, int n_in,
                              void* d_out, int out_size){
    const float* node_h  = (const float*)d_in[0];
    const float* edge_h  = (const float*)d_in[1];
    const float* msg_w0  = (const float*)d_in[2];
    const float* msg_b0  = (const float*)d_in[3];
    const float* msg_w1  = (const float*)d_in[4];
    const float* msg_b1  = (const float*)d_in[5];
    const float* msg_w2  = (const float*)d_in[6];
    const float* msg_b2  = (const float*)d_in[7];
    const float* ff_w0   = (const float*)d_in[8];
    const float* ff_b0   = (const float*)d_in[9];
    const float* ff_w1   = (const float*)d_in[10];
    const float* ff_b1   = (const float*)d_in[11];
    const float* edge_w0 = (const float*)d_in[12];
    const float* edge_b0 = (const float*)d_in[13];
    const float* edge_w1 = (const float*)d_in[14];
    const float* edge_b1 = (const float*)d_in[15];
    const float* edge_w2 = (const float*)d_in[16];
    const float* edge_b2 = (const float*)d_in[17];
    const float* ln1_g   = (const float*)d_in[18];
    const float* ln1_b   = (const float*)d_in[19];
    const float* ln2_g   = (const float*)d_in[20];
    const float* ln2_b   = (const float*)d_in[21];
    const float* lne_g   = (const float*)d_in[22];
    const float* lne_b   = (const float*)d_in[23];
    const int*   edge_idx= (const int*)  d_in[24];

    float* out_node = (float*)d_out;
    float* out_edge = out_node + (size_t)RES*H;

    const int SMEM_SMALL = (HH + 2*TILE_FLOATS) * 4;   // 114688
    cudaFuncSetAttribute(proj_kernel, cudaFuncAttributeMaxDynamicSharedMemorySize, SMEM_SMALL);
    cudaFuncSetAttribute(ff1_kernel,  cudaFuncAttributeMaxDynamicSharedMemorySize, SMEM_SMALL);
    cudaFuncSetAttribute(ff2_kernel,  cudaFuncAttributeMaxDynamicSharedMemorySize, SMEM_SMALL);
    cudaFuncSetAttribute(msg_mma_kernel,  cudaFuncAttributeMaxDynamicSharedMemorySize, SMEM_MMA);
    cudaFuncSetAttribute(edge_mma_kernel, cudaFuncAttributeMaxDynamicSharedMemorySize, SMEM_MMA);

    int dev = 0, nsm = 148;
    if (cudaGetDevice(&dev) == cudaSuccess){
        int v = 0;
        if (cudaDeviceGetAttribute(&v, cudaDevAttrMultiProcessorCount, dev) == cudaSuccess && v > 0)
            nsm = v;
    }

    const int NBLK = RES / 96;   // 125

    // W^T image prep (both stages)
    prep_wt_kernel<<<384, 128>>>(msg_w0 + 256*H,  msg_w1,  msg_w2,  0);
    prep_wt_kernel<<<384, 128>>>(edge_w0 + 256*H, edge_w1, edge_w2, 1);

    // msg stage projections: PA1 = node@W0a + b0, PB1 = node@W0b
    proj_kernel<<<NBLK, 256, SMEM_SMALL>>>(node_h, msg_w0,         msg_b0, 0);
    proj_kernel<<<NBLK, 256, SMEM_SMALL>>>(node_h, msg_w0 + 128*H, nullptr, 1);
    // msg MLP on tensor cores -> g_Y2
    msg_mma_kernel<<<nsm, 256, SMEM_MMA>>>(edge_h, edge_idx, msg_b1, msg_b2);
    // k-sum + LN1 -> NODE1
    ksum_kernel<<<RES, 128>>>(node_h, ln1_g, ln1_b);
    // feed-forward + LN2 -> out_node
    ff1_kernel<<<dim3(NBLK, 4), 256, SMEM_SMALL>>>(ff_w0, ff_b0);
    ff2_kernel<<<NBLK, 256, SMEM_SMALL>>>(ff_w1, ff_b1, ln2_g, ln2_b, out_node);
    // edge stage projections from refreshed nodes
    proj_kernel<<<NBLK, 256, SMEM_SMALL>>>(out_node, edge_w0,         edge_b0, 2);
    proj_kernel<<<NBLK, 256, SMEM_SMALL>>>(out_node, edge_w0 + 128*H, nullptr, 3);
    // edge MLP on tensor cores + residual + LNe -> out_edge
    edge_mma_kernel<<<nsm, 256, SMEM_MMA>>>(edge_h, edge_idx, edge_b1, edge_b2,
                                            lne_g, lne_b, out_edge);
    (void)in_sizes; (void)n_in; (void)out_size;
}

// round 17
// speedup vs baseline: 1.1954x; 1.0765x over previous
#include <cuda_runtime.h>
#include <cuda_bf16.h>
#include <math.h>
#include <stdint.h>

// ---------------------------------------------------------------------------
// EncoderLayer R17:
//  - msg stage: k-sum linearity => layer-2 GEMM moved from 576K edge rows to
//    12K residue rows (msg mma = 2 layers, both weight images RESIDENT in
//    smem, zero weight copies). New ksum2 + msg_fin kernels finish NODE1.
//  - fused 3-product gemm (AhBh + AhBl + AlBh share fragments): LDSM 18->12
//    per kstep.
//  - edge stage: R16 cp.async double-buffered 3-layer flow + fused gemm.
// ---------------------------------------------------------------------------

#define RES   12000
#define KN    48
#define H     128
#define HH    (H*H)
#define TILE_FLOATS (KN*H)
#define NEDGE (RES*KN)
#define NTILES (NEDGE/128)        // 4500

typedef unsigned long long u64;
typedef unsigned int u32;

// Scratch globals (sanctioned no-alloc path)
__device__ float g_PA1[RES*H];
__device__ float g_PB1[RES*H];
__device__ float g_PA2[RES*H];
__device__ float g_PB2[RES*H];
__device__ float g_NODE1[RES*H];
__device__ float g_FFH[(size_t)RES*4*H];     // also reused as XS scratch
__device__ float g_Y2[(size_t)NEDGE*H];      // msg x2 scratch
#define ASZ 34816                            // 128 rows * 272B
__device__ __align__(16) unsigned char g_WT[2][3][2*ASZ];

__device__ __forceinline__ float gelu(float x){
    return 0.5f * x * (1.0f + erff(x * 0.7071067811865475f));
}

// ---------------- packed f32x2 helpers (FFMA2 small kernels) ---------------
__device__ __forceinline__ u64 pk2(float x){
    u64 r; asm("mov.b64 %0, {%1, %1};" : "=l"(r) : "f"(x)); return r;
}
__device__ __forceinline__ u64 pk(float lo, float hi){
    u64 r; asm("mov.b64 %0, {%1, %2};" : "=l"(r) : "f"(lo), "f"(hi)); return r;
}
__device__ __forceinline__ u64 fma2(u64 a, u64 b, u64 c){
    u64 d; asm("fma.rn.f32x2 %0, %1, %2, %3;" : "=l"(d) : "l"(a), "l"(b), "l"(c)); return d;
}
__device__ __forceinline__ float2 up2(u64 v){
    float lo, hi; asm("mov.b64 {%0, %1}, %2;" : "=f"(lo), "=f"(hi) : "l"(v));
    return make_float2(lo, hi);
}

__device__ __forceinline__ void mm12(const float* __restrict__ xr,
                                     const float* __restrict__ ws,
                                     int tx, u64* __restrict__ acc){
    const float4* wp = (const float4*)ws + tx;
    #pragma unroll 1
    for (int k = 0; k < H; k += 4){
        float4 wk0 = wp[(k+0)*(H/4)];
        float4 wk1 = wp[(k+1)*(H/4)];
        float4 wk2 = wp[(k+2)*(H/4)];
        float4 wk3 = wp[(k+3)*(H/4)];
        u64 wl0 = pk(wk0.x, wk0.y), wh0 = pk(wk0.z, wk0.w);
        u64 wl1 = pk(wk1.x, wk1.y), wh1 = pk(wk1.z, wk1.w);
        u64 wl2 = pk(wk2.x, wk2.y), wh2 = pk(wk2.z, wk2.w);
        u64 wl3 = pk(wk3.x, wk3.y), wh3 = pk(wk3.z, wk3.w);
        #pragma unroll
        for (int r = 0; r < 12; r++){
            float4 xv = *(const float4*)(xr + r*H + k);
            u64* a = acc + r*2;
            u64 s;
            s = pk2(xv.x); a[0] = fma2(s, wl0, a[0]); a[1] = fma2(s, wh0, a[1]);
            s = pk2(xv.y); a[0] = fma2(s, wl1, a[0]); a[1] = fma2(s, wh1, a[1]);
            s = pk2(xv.z); a[0] = fma2(s, wl2, a[0]); a[1] = fma2(s, wh2, a[1]);
            s = pk2(xv.w); a[0] = fma2(s, wl3, a[0]); a[1] = fma2(s, wh3, a[1]);
        }
    }
}

template<int NT>
__device__ __forceinline__ void copyN(float* dst, const float* src, int tid, int nfloats){
    const float4* s = (const float4*)src; float4* d = (float4*)dst;
    #pragma unroll 4
    for (int i = tid; i < nfloats/4; i += NT) d[i] = s[i];
}

// ==================== FFMA2 kernels (proj / ff1 / ff2 / msg_fin) ===========
__global__ void __launch_bounds__(256, 2)
proj_kernel(const float* __restrict__ src, const float* __restrict__ w,
            const float* __restrict__ bias, int sel){
    extern __shared__ float sm[];
    float* ws = sm; float* xs = sm + HH;
    int tid = threadIdx.x, tx = tid & 31, ty = tid >> 5;
    copyN<256>(ws, w, tid, HH);
    copyN<256>(xs, src + (size_t)blockIdx.x*2*TILE_FLOATS, tid, 2*TILE_FLOATS);
    __syncthreads();
    u64 acc[24];
    #pragma unroll
    for (int q = 0; q < 24; q++) acc[q] = 0ull;
    mm12(xs + ty*12*H, ws, tx, acc);
    float4 bv = make_float4(0.f,0.f,0.f,0.f);
    if (bias) bv = *(const float4*)(bias + 4*tx);
    float* outp = (sel==0) ? g_PA1 : (sel==1) ? g_PB1 : (sel==2) ? g_PA2 : g_PB2;
    int base = blockIdx.x * 96 + ty*12;
    #pragma unroll
    for (int r = 0; r < 12; r++){
        float2 v0 = up2(acc[r*2]), v1 = up2(acc[r*2+1]);
        *(float4*)(outp + (size_t)(base+r)*H + 4*tx) =
            make_float4(v0.x+bv.x, v0.y+bv.y, v1.x+bv.z, v1.y+bv.w);
    }
}

// NODE1 = LN1(node_h + XS@W2 + 48*b2), XS in g_FFH[0 : RES*H]
__global__ void __launch_bounds__(256, 2)
msg_fin_kernel(const float* __restrict__ w2, const float* __restrict__ b2,
               const float* __restrict__ ln1_g, const float* __restrict__ ln1_b,
               const float* __restrict__ node_h){
    extern __shared__ float sm[];
    float* ws = sm; float* xs = sm + HH;
    int tid = threadIdx.x, tx = tid & 31, ty = tid >> 5;
    copyN<256>(ws, w2, tid, HH);
    copyN<256>(xs, g_FFH + (size_t)blockIdx.x*2*TILE_FLOATS, tid, 2*TILE_FLOATS);
    __syncthreads();
    u64 acc[24];
    #pragma unroll
    for (int q = 0; q < 24; q++) acc[q] = 0ull;
    mm12(xs + ty*12*H, ws, tx, acc);
    float4 bv = *(const float4*)(b2 + 4*tx);
    float4 lg = *(const float4*)(ln1_g + 4*tx);
    float4 lb = *(const float4*)(ln1_b + 4*tx);
    int base = blockIdx.x * 96 + ty*12;
    #pragma unroll
    for (int r = 0; r < 12; r++){
        int row = base + r;
        float4 a = *(const float4*)(node_h + (size_t)row*H + 4*tx);
        float2 v0 = up2(acc[r*2]), v1 = up2(acc[r*2+1]);
        float x0 = v0.x + 48.0f*bv.x + a.x, x1 = v0.y + 48.0f*bv.y + a.y;
        float x2 = v1.x + 48.0f*bv.z + a.z, x3 = v1.y + 48.0f*bv.w + a.w;
        float s = x0+x1+x2+x3, q = x0*x0+x1*x1+x2*x2+x3*x3;
        #pragma unroll
        for (int off = 16; off; off >>= 1){
            s += __shfl_xor_sync(0xffffffffu, s, off);
            q += __shfl_xor_sync(0xffffffffu, q, off);
        }
        float mean = s * (1.0f/H);
        float rstd = rsqrtf(q*(1.0f/H) - mean*mean + 1e-5f);
        *(float4*)(g_NODE1 + (size_t)row*H + 4*tx) =
            make_float4((x0-mean)*rstd*lg.x+lb.x, (x1-mean)*rstd*lg.y+lb.y,
                        (x2-mean)*rstd*lg.z+lb.z, (x3-mean)*rstd*lg.w+lb.w);
    }
}

__global__ void __launch_bounds__(256, 2)
ff1_kernel(const float* __restrict__ w, const float* __restrict__ bias){
    extern __shared__ float sm[];
    float* ws = sm; float* xs = sm + HH;
    int tid = threadIdx.x, tx = tid & 31, ty = tid >> 5;
    int n0 = blockIdx.y * H;
    {
        float4* d = (float4*)ws;
        #pragma unroll 4
        for (int i = tid; i < HH/4; i += 256){
            int k = i >> 5, c = i & 31;
            d[i] = *(const float4*)(w + (size_t)k*(4*H) + n0 + 4*c);
        }
    }
    copyN<256>(xs, g_NODE1 + (size_t)blockIdx.x*2*TILE_FLOATS, tid, 2*TILE_FLOATS);
    __syncthreads();
    u64 acc[24];
    #pragma unroll
    for (int q = 0; q < 24; q++) acc[q] = 0ull;
    mm12(xs + ty*12*H, ws, tx, acc);
    float4 bv = *(const float4*)(bias + n0 + 4*tx);
    int base = blockIdx.x * 96 + ty*12;
    #pragma unroll
    for (int r = 0; r < 12; r++){
        float2 v0 = up2(acc[r*2]), v1 = up2(acc[r*2+1]);
        *(float4*)(g_FFH + (size_t)(base+r)*(4*H) + n0 + 4*tx) =
            make_float4(gelu(v0.x+bv.x), gelu(v0.y+bv.y),
                        gelu(v1.x+bv.z), gelu(v1.y+bv.w));
    }
}

__global__ void __launch_bounds__(256, 2)
ff2_kernel(const float* __restrict__ w, const float* __restrict__ bias,
           const float* __restrict__ ln2_g, const float* __restrict__ ln2_b,
           float* __restrict__ out_node){
    extern __shared__ float sm[];
    float* ws = sm; float* xs = sm + HH;
    int tid = threadIdx.x, tx = tid & 31, ty = tid >> 5;
    int base = blockIdx.x * 96;
    u64 acc[24];
    #pragma unroll
    for (int q = 0; q < 24; q++) acc[q] = 0ull;
    for (int c = 0; c < 4; c++){
        copyN<256>(ws, w + (size_t)c*H*H, tid, HH);
        {
            float4* d = (float4*)xs;
            #pragma unroll
            for (int i = tid; i < 2*TILE_FLOATS/4; i += 256){
                int m = i >> 5, cc = i & 31;
                d[i] = *(const float4*)(g_FFH + (size_t)(base+m)*(4*H) + c*H + 4*cc);
            }
        }
        __syncthreads();
        mm12(xs + ty*12*H, ws, tx, acc);
        __syncthreads();
    }
    float4 bv = *(const float4*)(bias + 4*tx);
    float4 lg = *(const float4*)(ln2_g + 4*tx);
    float4 lb = *(const float4*)(ln2_b + 4*tx);
    #pragma unroll
    for (int r = 0; r < 12; r++){
        int row = base + ty*12 + r;
        float4 a = *(const float4*)(g_NODE1 + (size_t)row*H + 4*tx);
        float2 v0 = up2(acc[r*2]), v1 = up2(acc[r*2+1]);
        float x0 = v0.x+bv.x+a.x, x1 = v0.y+bv.y+a.y;
        float x2 = v1.x+bv.z+a.z, x3 = v1.y+bv.w+a.w;
        float s = x0+x1+x2+x3, q = x0*x0+x1*x1+x2*x2+x3*x3;
        #pragma unroll
        for (int off = 16; off; off >>= 1){
            s += __shfl_xor_sync(0xffffffffu, s, off);
            q += __shfl_xor_sync(0xffffffffu, q, off);
        }
        float mean = s * (1.0f/H);
        float rstd = rsqrtf(q*(1.0f/H) - mean*mean + 1e-5f);
        *(float4*)(out_node + (size_t)row*H + 4*tx) =
            make_float4((x0-mean)*rstd*lg.x+lb.x, (x1-mean)*rstd*lg.y+lb.y,
                        (x2-mean)*rstd*lg.z+lb.z, (x3-mean)*rstd*lg.w+lb.w);
    }
}

// ===================== mma.sync machinery (base target) ====================
#define PKB 272
#define OFF_A    1024
#define OFF_B0   (OFF_A + 2*ASZ)              // 70656
#define OFF_B1   (OFF_B0 + 2*ASZ)             // 140288
#define OFF_RED  (OFF_B1 + 2*ASZ)             // 209920 (2KB)
#define OFF_BIAS (OFF_RED + 2048)             // 211968 (2KB)
#define SMEM_MMA (OFF_BIAS + 2048)            // 214016

__device__ __forceinline__ u32 smem_u32(const void* p){
    u32 a;
    asm("{ .reg .u64 t; cvta.to.shared.u64 t, %1; cvt.u32.u64 %0, t; }"
        : "=r"(a) : "l"(p));
    return a;
}
__device__ __forceinline__ void ldsm4(u32 r[4], u32 addr){
    asm volatile("ldmatrix.sync.aligned.m8n8.x4.shared.b16 {%0,%1,%2,%3}, [%4];"
        : "=r"(r[0]), "=r"(r[1]), "=r"(r[2]), "=r"(r[3]) : "r"(addr));
}
__device__ __forceinline__ void mma_bf16(float* d, const u32* a, const u32* b){
    asm volatile("mma.sync.aligned.m16n8k16.row.col.f32.bf16.bf16.f32 "
        "{%0,%1,%2,%3}, {%4,%5,%6,%7}, {%8,%9}, {%0,%1,%2,%3};"
        : "+f"(d[0]), "+f"(d[1]), "+f"(d[2]), "+f"(d[3])
        : "r"(a[0]), "r"(a[1]), "r"(a[2]), "r"(a[3]), "r"(b[0]), "r"(b[1]));
}
__device__ __forceinline__ void split2(float x, float y, u32& hi, u32& lo){
    __nv_bfloat16 hx = __float2bfloat16_rn(x), hy = __float2bfloat16_rn(y);
    float rx = x - __bfloat162float(hx), ry = y - __bfloat162float(hy);
    __nv_bfloat16 lx = __float2bfloat16_rn(rx), ly = __float2bfloat16_rn(ry);
    hi = (u32)__bfloat16_as_ushort(hx) | ((u32)__bfloat16_as_ushort(hy) << 16);
    lo = (u32)__bfloat16_as_ushort(lx) | ((u32)__bfloat16_as_ushort(ly) << 16);
}

// fused 3-product split GEMM: acc += Ah*Bh + Ah*Bl + Al*Bh.
// warp tile rows mw*32..+31, cols nw*64..+63. LDSM 12/kstep (was 18).
__device__ __forceinline__ void gemm3f(u32 abase_, u32 bbase_, int lane, int mw, int nw,
                                       float acc[2][8][4]){
    #pragma unroll
    for (int mt = 0; mt < 2; mt++)
        #pragma unroll
        for (int nt = 0; nt < 8; nt++)
            #pragma unroll
            for (int c = 0; c < 4; c++) acc[mt][nt][c] = 0.f;
    u32 aoff = (u32)(mw*32 + (lane & 15))*PKB + (u32)((lane >> 4) * 16);
    u32 boff = (u32)(nw*64 + ((lane >> 4) << 3) + (lane & 7))*PKB
             + (u32)(((lane >> 3) & 1) * 16);
    u32 ah = abase_ + aoff, al = ah + ASZ;
    u32 bh = bbase_ + boff, bl = bh + ASZ;
    #pragma unroll 1
    for (int ks = 0; ks < 8; ks++){
        u32 kb = (u32)(ks*32);
        u32 Ah0[4], Ah1[4], Al0[4], Al1[4], Bh[4][4], Bl[4][4];
        ldsm4(Ah0, ah + kb);
        ldsm4(Ah1, ah + 16*PKB + kb);
        ldsm4(Al0, al + kb);
        ldsm4(Al1, al + 16*PKB + kb);
        #pragma unroll
        for (int q = 0; q < 4; q++){
            ldsm4(Bh[q], bh + q*16*PKB + kb);
            ldsm4(Bl[q], bl + q*16*PKB + kb);
        }
        #pragma unroll
        for (int mt = 0; mt < 2; mt++){
            #pragma unroll
            for (int nt = 0; nt < 8; nt++){
                const u32* bph = &Bh[nt>>1][(nt&1)*2];
                const u32* bpl = &Bl[nt>>1][(nt&1)*2];
                mma_bf16(acc[mt][nt], mt ? Ah1 : Ah0, bph);
                mma_bf16(acc[mt][nt], mt ? Ah1 : Ah0, bpl);
                mma_bf16(acc[mt][nt], mt ? Al1 : Al0, bph);
            }
        }
    }
}

// synchronous 68KB weight copy (used once per kernel for resident buffers)
__device__ __forceinline__ void copyB(char* dst, const unsigned char* src, int tid){
    uint4* d = (uint4*)dst; const uint4* s = (const uint4*)src;
    #pragma unroll
    for (int i = tid; i < (2*ASZ)/16; i += 256) d[i] = s[i];
}
// truly asynchronous 68KB weight copy (cp.async, one commit group)
__device__ __forceinline__ void copyB_async(u32 dst, const unsigned char* src, int tid){
    #pragma unroll
    for (int i = tid; i < (2*ASZ)/16; i += 256){
        asm volatile("cp.async.cg.shared.global [%0], [%1], 16;"
            :: "r"(dst + (u32)i*16), "l"(src + (size_t)i*16));
    }
    asm volatile("cp.async.commit_group;" ::: "memory");
}
#define CP_WAIT1() asm volatile("cp.async.wait_group 1;" ::: "memory")

// build A hi/lo images from a 128x128 fp32 tile (256 threads)
__device__ __forceinline__ void buildA(char* Ahi, char* Alo,
                                       const float* __restrict__ src128, int tid){
    int row = tid & 127, half = tid >> 7;
    const float2* src = (const float2*)(src128 + (size_t)row*H + half*64);
    u32 base = (u32)row*PKB + (u32)half*128;
    #pragma unroll
    for (int j = 0; j < 32; j++){
        float2 v = src[j];
        u32 hi, lo; split2(v.x, v.y, hi, lo);
        *(u32*)(Ahi + base + 4*j) = hi;
        *(u32*)(Alo + base + 4*j) = lo;
    }
}

// prebuild W^T hi/lo images, padded
__global__ void prep_wt_kernel(const float* __restrict__ w0,
                               const float* __restrict__ w1,
                               const float* __restrict__ w2, int stage){
    int bx = blockIdx.x;              // 384 = 3 mats * 128 n-rows
    int mat = bx >> 7, n = bx & 127, k = threadIdx.x;
    const float* w = (mat==0) ? w0 : (mat==1) ? w1 : w2;
    float x = w[k*H + n];             // B^T[n][k] = W[k][n]
    __nv_bfloat16 h = __float2bfloat16_rn(x);
    float l = x - __bfloat162float(h);
    __nv_bfloat16 hl = __float2bfloat16_rn(l);
    u32 off = (u32)n*PKB + (u32)k*2;
    *(__nv_bfloat16*)(&g_WT[stage][mat][0]   + off) = h;
    *(__nv_bfloat16*)(&g_WT[stage][mat][ASZ] + off) = hl;
}

// ---------------------- msg stage mma kernel (2 layers) --------------------
__global__ void __launch_bounds__(256, 1)
msg_mma_kernel(const float* __restrict__ edge_h, const int* __restrict__ edge_idx,
               const float* __restrict__ b1){
    extern __shared__ char smc[];
    u32 sb = smem_u32(smc);
    char* Ahi = smc + OFF_A; char* Alo = Ahi + ASZ;
    float* sb1 = (float*)(smc + OFF_BIAS);
    int tid = threadIdx.x, lane = tid & 31, w = tid >> 5;
    int mw = w & 3, nw = w >> 2;
    int g = lane >> 2, t2 = (lane & 3)*2;
    u32 abase = sb + OFF_A;
    if (tid < 128) sb1[tid] = b1[tid];
    copyB(smc + OFF_B0, g_WT[0][0], tid);        // W0c resident
    copyB(smc + OFF_B1, g_WT[0][1], tid);        // W1 resident
    // (loop-top barrier makes these visible before first gemm)

    for (int tile = blockIdx.x; tile < NTILES; tile += gridDim.x){
        buildA(Ahi, Alo, edge_h + (size_t)tile*128*H, tid);
        int rows[4], jr4[4], ir4[4];
        #pragma unroll
        for (int idx = 0; idx < 4; idx++){
            rows[idx] = mw*32 + (idx>>1)*16 + (idx&1)*8 + g;
            int gr = tile*128 + rows[idx];
            ir4[idx] = gr/48; jr4[idx] = edge_idx[gr];
        }
        __syncthreads();                          // A (+resident B) visible

        // layer 0
        float acc[2][8][4];
        gemm3f(abase, sb + OFF_B0, lane, mw, nw, acc);
        __syncthreads();                          // A reads complete
        #pragma unroll
        for (int mt = 0; mt < 2; mt++)
        #pragma unroll
        for (int rr = 0; rr < 2; rr++){
            int idx = mt*2 + rr, row = rows[idx];
            const float* pa = g_PA1 + (size_t)ir4[idx]*H;
            const float* pb = g_PB1 + (size_t)jr4[idx]*H;
            #pragma unroll
            for (int nt = 0; nt < 8; nt++){
                int col = nw*64 + nt*8 + t2;
                float2 a = *(const float2*)(pa + col);
                float2 b = *(const float2*)(pb + col);
                float v0 = gelu(acc[mt][nt][rr*2]   + a.x + b.x);
                float v1 = gelu(acc[mt][nt][rr*2+1] + a.y + b.y);
                u32 hi, lo; split2(v0, v1, hi, lo);
                u32 off = (u32)row*PKB + (u32)col*2;
                *(u32*)(Ahi + off) = hi; *(u32*)(Alo + off) = lo;
            }
        }
        __syncthreads();                          // new A visible

        // layer 1 -> x2 to gmem
        gemm3f(abase, sb + OFF_B1, lane, mw, nw, acc);
        __syncthreads();                          // A reads done (next buildA)
        #pragma unroll
        for (int mt = 0; mt < 2; mt++)
        #pragma unroll
        for (int rr = 0; rr < 2; rr++){
            int idx = mt*2 + rr;
            size_t gr = (size_t)tile*128 + rows[idx];
            #pragma unroll
            for (int nt = 0; nt < 8; nt++){
                int col = nw*64 + nt*8 + t2;
                *(float2*)(g_Y2 + gr*H + col) = make_float2(
                    gelu(acc[mt][nt][rr*2]   + sb1[col]),
                    gelu(acc[mt][nt][rr*2+1] + sb1[col+1]));
            }
        }
    }
}

// ---------------------- edge stage mma kernel (3 layers) -------------------
__global__ void __launch_bounds__(256, 1)
edge_mma_kernel(const float* __restrict__ edge_h, const int* __restrict__ edge_idx,
                const float* __restrict__ b1, const float* __restrict__ b2,
                const float* __restrict__ lne_g, const float* __restrict__ lne_b,
                float* __restrict__ out_edge){
    extern __shared__ char smc[];
    u32 sb = smem_u32(smc);
    char* Ahi = smc + OFF_A; char* Alo = Ahi + ASZ;
    float2* red = (float2*)(smc + OFF_RED);       // [row*2 + nw]
    float* sb1 = (float*)(smc + OFF_BIAS);
    float* sb2 = sb1 + 128;
    float* slg = sb2 + 128;
    float* slb = slg + 128;
    int tid = threadIdx.x, lane = tid & 31, w = tid >> 5;
    int mw = w & 3, nw = w >> 2;
    int g = lane >> 2, t2 = (lane & 3)*2;
    u32 abase = sb + OFF_A;
    if (tid < 128){ sb1[tid]=b1[tid]; sb2[tid]=b2[tid]; slg[tid]=lne_g[tid]; slb[tid]=lne_b[tid]; }
    int buf = 0;
    copyB_async(sb + OFF_B0, g_WT[1][0], tid);

    for (int tile = blockIdx.x; tile < NTILES; tile += gridDim.x){
        buildA(Ahi, Alo, edge_h + (size_t)tile*128*H, tid);
        copyB_async(sb + (buf ? OFF_B0 : OFF_B1), g_WT[1][1], tid);
        int rows[4], jr4[4], ir4[4];
        #pragma unroll
        for (int idx = 0; idx < 4; idx++){
            rows[idx] = mw*32 + (idx>>1)*16 + (idx&1)*8 + g;
            int gr = tile*128 + rows[idx];
            ir4[idx] = gr/48; jr4[idx] = edge_idx[gr];
        }
        #pragma unroll 1
        for (int layer = 0; layer < 3; layer++){
            CP_WAIT1();
            __syncthreads();
            u32 bb = sb + (((layer == 1) ? (buf ^ 1) : buf) ? OFF_B1 : OFF_B0);
            float acc[2][8][4];
            gemm3f(abase, bb, lane, mw, nw, acc);
            __syncthreads();
            if (layer == 0)
                copyB_async(sb + (buf ? OFF_B1 : OFF_B0), g_WT[1][2], tid);
            else if (layer == 1)
                copyB_async(sb + (buf ? OFF_B0 : OFF_B1), g_WT[1][0], tid);
            if (layer < 2){
                #pragma unroll
                for (int mt = 0; mt < 2; mt++)
                #pragma unroll
                for (int rr = 0; rr < 2; rr++){
                    int idx = mt*2 + rr, row = rows[idx];
                    const float* pa = g_PA2 + (size_t)ir4[idx]*H;
                    const float* pb = g_PB2 + (size_t)jr4[idx]*H;
                    #pragma unroll
                    for (int nt = 0; nt < 8; nt++){
                        int col = nw*64 + nt*8 + t2;
                        float v0 = acc[mt][nt][rr*2], v1 = acc[mt][nt][rr*2+1];
                        if (layer == 0){
                            float2 a = *(const float2*)(pa + col);
                            float2 b = *(const float2*)(pb + col);
                            v0 = gelu(v0 + a.x + b.x); v1 = gelu(v1 + a.y + b.y);
                        } else {
                            v0 = gelu(v0 + sb1[col]); v1 = gelu(v1 + sb1[col+1]);
                        }
                        u32 hi, lo; split2(v0, v1, hi, lo);
                        u32 off = (u32)row*PKB + (u32)col*2;
                        *(u32*)(Ahi + off) = hi; *(u32*)(Alo + off) = lo;
                    }
                }
            } else {
                // x = D + b2 + edge_h ; per-row LN across the 2 nw halves
                #pragma unroll
                for (int mt = 0; mt < 2; mt++)
                #pragma unroll
                for (int rr = 0; rr < 2; rr++){
                    int idx = mt*2 + rr;
                    size_t gr = (size_t)tile*128 + rows[idx];
                    const float* eh = edge_h + gr*H;
                    float s = 0.f, q = 0.f;
                    #pragma unroll
                    for (int nt = 0; nt < 8; nt++){
                        int col = nw*64 + nt*8 + t2;
                        float2 e = *(const float2*)(eh + col);
                        float v0 = acc[mt][nt][rr*2]   + sb2[col]   + e.x;
                        float v1 = acc[mt][nt][rr*2+1] + sb2[col+1] + e.y;
                        acc[mt][nt][rr*2] = v0; acc[mt][nt][rr*2+1] = v1;
                        s += v0 + v1; q += v0*v0 + v1*v1;
                    }
                    s += __shfl_xor_sync(0xffffffffu, s, 1);
                    q += __shfl_xor_sync(0xffffffffu, q, 1);
                    s += __shfl_xor_sync(0xffffffffu, s, 2);
                    q += __shfl_xor_sync(0xffffffffu, q, 2);
                    if ((lane & 3) == 0) red[rows[idx]*2 + nw] = make_float2(s, q);
                }
                __syncthreads();
                #pragma unroll
                for (int mt = 0; mt < 2; mt++)
                #pragma unroll
                for (int rr = 0; rr < 2; rr++){
                    int idx = mt*2 + rr;
                    size_t gr = (size_t)tile*128 + rows[idx];
                    float2 r0 = red[rows[idx]*2], r1 = red[rows[idx]*2 + 1];
                    float mean = (r0.x + r1.x) * (1.0f/H);
                    float var  = (r0.y + r1.y) * (1.0f/H) - mean*mean;
                    float rstd = rsqrtf(var + 1e-5f);
                    #pragma unroll
                    for (int nt = 0; nt < 8; nt++){
                        int col = nw*64 + nt*8 + t2;
                        float v0 = acc[mt][nt][rr*2], v1 = acc[mt][nt][rr*2+1];
                        *(float2*)(out_edge + gr*H + col) = make_float2(
                            (v0-mean)*rstd*slg[col]   + slb[col],
                            (v1-mean)*rstd*slg[col+1] + slb[col+1]);
                    }
                }
            }
        }
        buf ^= 1;
    }
}

// ---------------- k-sum of x2 (g_Y2) -> XS (g_FFH) -------------------------
__global__ void __launch_bounds__(128)
ksum2_kernel(){
    int i = blockIdx.x, c = threadIdx.x;
    const float* y = g_Y2 + (size_t)i*KN*H + c;
    float s = 0.f;
    #pragma unroll 8
    for (int k = 0; k < KN; k++) s += y[(size_t)k*H];
    g_FFH[(size_t)i*H + c] = s;
}

// ---------------------------------------------------------------------------
extern "C" void kernel_launch(void* const* d_in, const int* in_sizes, int n_in,
                              void* d_out, int out_size){
    const float* node_h  = (const float*)d_in[0];
    const float* edge_h  = (const float*)d_in[1];
    const float* msg_w0  = (const float*)d_in[2];
    const float* msg_b0  = (const float*)d_in[3];
    const float* msg_w1  = (const float*)d_in[4];
    const float* msg_b1  = (const float*)d_in[5];
    const float* msg_w2  = (const float*)d_in[6];
    const float* msg_b2  = (const float*)d_in[7];
    const float* ff_w0   = (const float*)d_in[8];
    const float* ff_b0   = (const float*)d_in[9];
    const float* ff_w1   = (const float*)d_in[10];
    const float* ff_b1   = (const float*)d_in[11];
    const float* edge_w0 = (const float*)d_in[12];
    const float* edge_b0 = (const float*)d_in[13];
    const float* edge_w1 = (const float*)d_in[14];
    const float* edge_b1 = (const float*)d_in[15];
    const float* edge_w2 = (const float*)d_in[16];
    const float* edge_b2 = (const float*)d_in[17];
    const float* ln1_g   = (const float*)d_in[18];
    const float* ln1_b   = (const float*)d_in[19];
    const float* ln2_g   = (const float*)d_in[20];
    const float* ln2_b   = (const float*)d_in[21];
    const float* lne_g   = (const float*)d_in[22];
    const float* lne_b   = (const float*)d_in[23];
    const int*   edge_idx= (const int*)  d_in[24];

    float* out_node = (float*)d_out;
    float* out_edge = out_node + (size_t)RES*H;

    const int SMEM_SMALL = (HH + 2*TILE_FLOATS) * 4;   // 114688
    cudaFuncSetAttribute(proj_kernel,    cudaFuncAttributeMaxDynamicSharedMemorySize, SMEM_SMALL);
    cudaFuncSetAttribute(msg_fin_kernel, cudaFuncAttributeMaxDynamicSharedMemorySize, SMEM_SMALL);
    cudaFuncSetAttribute(ff1_kernel,     cudaFuncAttributeMaxDynamicSharedMemorySize, SMEM_SMALL);
    cudaFuncSetAttribute(ff2_kernel,     cudaFuncAttributeMaxDynamicSharedMemorySize, SMEM_SMALL);
    cudaFuncSetAttribute(msg_mma_kernel,  cudaFuncAttributeMaxDynamicSharedMemorySize, SMEM_MMA);
    cudaFuncSetAttribute(edge_mma_kernel, cudaFuncAttributeMaxDynamicSharedMemorySize, SMEM_MMA);

    int dev = 0, nsm = 148;
    if (cudaGetDevice(&dev) == cudaSuccess){
        int v = 0;
        if (cudaDeviceGetAttribute(&v, cudaDevAttrMultiProcessorCount, dev) == cudaSuccess && v > 0)
            nsm = v;
    }

    const int NBLK = RES / 96;   // 125

    // W^T image prep (both stages)
    prep_wt_kernel<<<384, 128>>>(msg_w0 + 256*H,  msg_w1,  msg_w2,  0);
    prep_wt_kernel<<<384, 128>>>(edge_w0 + 256*H, edge_w1, edge_w2, 1);

    // msg stage projections: PA1 = node@W0a + b0, PB1 = node@W0b
    proj_kernel<<<NBLK, 256, SMEM_SMALL>>>(node_h, msg_w0,         msg_b0, 0);
    proj_kernel<<<NBLK, 256, SMEM_SMALL>>>(node_h, msg_w0 + 128*H, nullptr, 1);
    // msg MLP layers 0-1 on tensor cores -> x2 in g_Y2
    msg_mma_kernel<<<nsm, 256, SMEM_MMA>>>(edge_h, edge_idx, msg_b1);
    // k-sum of x2 -> XS (g_FFH)
    ksum2_kernel<<<RES, 128>>>();
    // NODE1 = LN1(node_h + XS@W2 + 48*b2)
    msg_fin_kernel<<<NBLK, 256, SMEM_SMALL>>>(msg_w2, msg_b2, ln1_g, ln1_b, node_h);
    // feed-forward + LN2 -> out_node
    ff1_kernel<<<dim3(NBLK, 4), 256, SMEM_SMALL>>>(ff_w0, ff_b0);
    ff2_kernel<<<NBLK, 256, SMEM_SMALL>>>(ff_w1, ff_b1, ln2_g, ln2_b, out_node);
    // edge stage projections from refreshed nodes
    proj_kernel<<<NBLK, 256, SMEM_SMALL>>>(out_node, edge_w0,         edge_b0, 2);
    proj_kernel<<<NBLK, 256, SMEM_SMALL>>>(out_node, edge_w0 + 128*H, nullptr, 3);
    // edge MLP on tensor cores + residual + LNe -> out_edge
    edge_mma_kernel<<<nsm, 256, SMEM_MMA>>>(edge_h, edge_idx, edge_b1, edge_b2,
                                            lne_g, lne_b, out_edge);
    (void)in_sizes; (void)n_in; (void)out_size;
}